// round 5
// baseline (speedup 1.0000x reference)
#include <cuda_runtime.h>
#include <cuda_fp16.h>
#include <cstdint>

// Problem constants
#define NB 16     // batch
#define NP 1024   // primary caps
#define NJ 32     // out caps
#define NE 64     // Dp (contraction)
#define ND 64     // D

// K1 tiling
#define JG 8      // j's per CTA
#define EC 16     // e-chunk for cp.async pipeline

// Route tiling: 128-thread CTAs (4 warps), PW p per warp, 64 CTAs per b
#define PW 4
#define RCTAB 64  // route CTAs per batch image (64*4 warps * 4 p = 1024 p)

#define SLOTS 64  // spart slots per b (both psum and route produce 64)

// u inner-block (2048 elems per (b,p)) is PERMUTED: index(dp,j,par) = dp*64 + j*2 + par
// where d = 2*dp + par.  g_vj0/g_vj1/g_spart use the same permuted layout.

// ---------------- scratch ----------------------------------------------------
__device__ __half g_u[(size_t)NB * NP * NJ * ND];        // 67 MB fp16, permuted
__device__ float g_spart[(size_t)NB * SLOTS * NJ * ND];  // 8.4 MB partials, permuted
__device__ float g_vj0[NB * NJ * ND];                    // permuted
__device__ float g_vj1[NB * NJ * ND];                    // permuted
__device__ float g_bij[NB * NP * NJ];

// ---------------- f32x2 helpers ---------------------------------------------
__device__ __forceinline__ unsigned long long pack2(float x, float y) {
    unsigned long long r;
    asm("mov.b64 %0, {%1,%2};" : "=l"(r) : "f"(x), "f"(y));
    return r;
}
__device__ __forceinline__ float2 unpack2(unsigned long long v) {
    float2 r;
    asm("mov.b64 {%0,%1}, %2;" : "=f"(r.x), "=f"(r.y) : "l"(v));
    return r;
}
__device__ __forceinline__ void ffma2(unsigned long long& acc,
                                      unsigned long long a, unsigned long long b) {
    asm("fma.rn.f32x2 %0, %1, %2, %0;" : "+l"(acc) : "l"(a), "l"(b));
}
__device__ __forceinline__ void cpasync16(void* dst, const void* src) {
    uint32_t s = (uint32_t)__cvta_generic_to_shared(dst);
    asm volatile("cp.async.cg.shared.global [%0], [%1], 16;" :: "r"(s), "l"(src));
}

// =============================================================================
// K1: u[b,p,j,d] = sum_e inp[b,p,e] * W[p,j,e,d] + bias[p,j,d]
// fp16 store into PERMUTED layout via smem staging (full-sector coalesced).
// =============================================================================
extern __shared__ float k1_smem[];

__global__ __launch_bounds__(128, 3) void k_gemm(const float* __restrict__ inp,
                                                 const float* __restrict__ W,
                                                 const float* __restrict__ bias) {
    float* Ws    = k1_smem;                     // [2][JG][EC][ND] = 64 KB
    float* inp_t = k1_smem + 2 * JG * EC * ND;  // [NE][NB], 4 KB

    const int p   = blockIdx.x;
    const int jg  = blockIdx.y;
    const int tid = threadIdx.x;

    {
        int b = tid >> 3, e0 = (tid & 7) << 3;
        const float4* src = (const float4*)(inp + ((size_t)b * NP + p) * NE + e0);
        float4 v0 = src[0], v1 = src[1];
        float v[8] = {v0.x, v0.y, v0.z, v0.w, v1.x, v1.y, v1.z, v1.w};
#pragma unroll
        for (int k = 0; k < 8; k++) inp_t[(e0 + k) * NB + b] = v[k];
    }

    const float* Wbase = W + ((size_t)p * NJ + (size_t)jg * JG) * NE * ND;

    auto prefetch = [&](int c, int buf) {
#pragma unroll
        for (int i = 0; i < 16; i++) {
            int ft  = i * 128 + tid;
            int j   = ft >> 8;
            int rem = ft & 255;
            int el  = rem >> 4;
            int d4  = rem & 15;
            const float* src = Wbase + ((size_t)j * NE + (c * EC + el)) * ND + d4 * 4;
            float* dst = Ws + (((size_t)buf * JG + j) * EC + el) * ND + d4 * 4;
            cpasync16(dst, src);
        }
        asm volatile("cp.async.commit_group;");
    };

    prefetch(0, 0);
    prefetch(1, 1);
    __syncthreads();

    const int jl = tid >> 4;
    const int r  = tid & 15;
    const int b0 = (r & 1) << 3;
    const int d0 = (r >> 1) << 3;

    unsigned long long acc[8][4];
#pragma unroll
    for (int i = 0; i < 8; i++)
#pragma unroll
        for (int k = 0; k < 4; k++) acc[i][k] = 0ull;

#pragma unroll 1
    for (int c = 0; c < 4; c++) {
        if (c < 3) asm volatile("cp.async.wait_group 1;");
        else       asm volatile("cp.async.wait_group 0;");
        __syncthreads();
        const float* wrow = Ws + (((size_t)(c & 1) * JG + jl) * EC) * ND + d0;
        const float* irow = inp_t + (size_t)(c * EC) * NB + b0;
#pragma unroll
        for (int el = 0; el < EC; el++) {
            const ulonglong2* wp = (const ulonglong2*)(wrow + (size_t)el * ND);
            ulonglong2 w0 = wp[0], w1 = wp[1];
            float4 i0 = *(const float4*)(irow + (size_t)el * NB);
            float4 i1 = *(const float4*)(irow + (size_t)el * NB + 4);
            float ia[8] = {i0.x, i0.y, i0.z, i0.w, i1.x, i1.y, i1.z, i1.w};
#pragma unroll
            for (int bi = 0; bi < 8; bi++) {
                unsigned long long av = pack2(ia[bi], ia[bi]);
                ffma2(acc[bi][0], av, w0.x);
                ffma2(acc[bi][1], av, w0.y);
                ffma2(acc[bi][2], av, w1.x);
                ffma2(acc[bi][3], av, w1.y);
            }
        }
        __syncthreads();
        if (c + 2 < 4) prefetch(c + 2, c & 1);
    }
    // all warps past last read of Ws -> reuse smem for the staging buffer

    // ---- stage fp16 tile: stage_h2[(b*32 + dp)*8 + jl] ----
    __half2* stage = (__half2*)k1_smem;   // 16 KB
    const int dp0 = d0 >> 1;
    const float* bptr = bias + ((size_t)p * NJ + (jg * JG + jl)) * ND + d0;
    float4 bb0 = *(const float4*)(bptr);
    float4 bb1 = *(const float4*)(bptr + 4);
    float bb[8] = {bb0.x, bb0.y, bb0.z, bb0.w, bb1.x, bb1.y, bb1.z, bb1.w};
#pragma unroll
    for (int bi = 0; bi < 8; bi++) {
        float2 v0 = unpack2(acc[bi][0]);
        float2 v1 = unpack2(acc[bi][1]);
        float2 v2 = unpack2(acc[bi][2]);
        float2 v3 = unpack2(acc[bi][3]);
        float fv[8] = {v0.x, v0.y, v1.x, v1.y, v2.x, v2.y, v3.x, v3.y};
        const int b = b0 + bi;
#pragma unroll
        for (int k = 0; k < 4; k++) {
            stage[((b * 32) + (dp0 + k)) * 8 + jl] =
                __floats2half2_rn(fv[2 * k] + bb[2 * k], fv[2 * k + 1] + bb[2 * k + 1]);
        }
    }
    __syncthreads();

    // ---- coalesced permuted store: 1024 float4 chunks, 8 per thread ----
#pragma unroll
    for (int i = 0; i < 8; i++) {
        int idx = i * 128 + tid;
        int b   = idx >> 6;
        int dp  = (idx & 63) >> 1;
        int sel = idx & 1;
        float4 v = *(const float4*)(stage + ((b * 32) + dp) * 8 + sel * 4);
        __half* gdst = g_u + ((size_t)b * NP + p) * (NJ * ND)
                           + (size_t)dp * (NJ * 2) + jg * 16 + sel * 8;
        *(float4*)gdst = v;
    }
}

// =============================================================================
// K2: partial sum over p for iteration 0 (uniform c).  Layout-agnostic.
// =============================================================================
__global__ void k_psum() {
    int ch = blockIdx.x;   // 64 chunks of 16 p
    int b  = blockIdx.y;
    int t  = threadIdx.x;  // 256, 8 elems each
    float acc[8];
#pragma unroll
    for (int k = 0; k < 8; k++) acc[k] = 0.f;
    size_t base = (((size_t)b * NP) + (size_t)ch * 16) * (NJ * ND) + (size_t)t * 8;
#pragma unroll
    for (int pi = 0; pi < 16; pi++) {
        uint4 raw = *(const uint4*)(g_u + base + (size_t)pi * (NJ * ND));
        const __half2* h = (const __half2*)&raw;
#pragma unroll
        for (int k = 0; k < 4; k++) {
            float2 f = __half22float2(h[k]);
            acc[2 * k]     += f.x;
            acc[2 * k + 1] += f.y;
        }
    }
    float* dst = g_spart + ((size_t)b * SLOTS + ch) * (NJ * ND) + (size_t)t * 8;
    *(float4*)dst       = make_float4(acc[0], acc[1], acc[2], acc[3]);
    *(float4*)(dst + 4) = make_float4(acc[4], acc[5], acc[6], acc[7]);
}

// =============================================================================
// K3: reduce 64 partials + squash.  grid(NB), 256 threads.
// =============================================================================
__global__ void k_squash(float scale, int which, float* __restrict__ outext) {
    __shared__ float s2s[NJ];
    int b = blockIdx.x, t = threadIdx.x;
    float acc[8];
#pragma unroll
    for (int k = 0; k < 8; k++) acc[k] = 0.f;
    size_t base = (size_t)b * SLOTS * (NJ * ND) + (size_t)t * 8;
#pragma unroll 4
    for (int k = 0; k < SLOTS; k++) {
        const float4* r4 = (const float4*)(g_spart + base + (size_t)k * (NJ * ND));
        float4 v0 = r4[0], v1 = r4[1];
        acc[0] += v0.x; acc[1] += v0.y; acc[2] += v0.z; acc[3] += v0.w;
        acc[4] += v1.x; acc[5] += v1.y; acc[6] += v1.z; acc[7] += v1.w;
    }
#pragma unroll
    for (int k = 0; k < 8; k++) acc[k] *= scale;

    if (t < NJ) s2s[t] = 0.f;
    __syncthreads();
    int dp = t >> 3;
    int j0 = (t & 7) * 4;
#pragma unroll
    for (int q = 0; q < 4; q++)
        atomicAdd(&s2s[j0 + q], acc[2 * q] * acc[2 * q] + acc[2 * q + 1] * acc[2 * q + 1]);
    __syncthreads();

    if (which < 2) {
        float* out = (which == 0) ? g_vj0 : g_vj1;
        float* dst = out + (size_t)b * (NJ * ND) + (size_t)t * 8;
#pragma unroll
        for (int q = 0; q < 4; q++) {
            float s2 = s2s[j0 + q];
            float f = sqrtf(s2) / (1.0f + s2);
            dst[2 * q]     = acc[2 * q] * f;
            dst[2 * q + 1] = acc[2 * q + 1] * f;
        }
    } else {
        float* dst = outext + (size_t)b * (NJ * ND);
#pragma unroll
        for (int q = 0; q < 4; q++) {
            float s2 = s2s[j0 + q];
            float f = sqrtf(s2) / (1.0f + s2);
            dst[(j0 + q) * ND + 2 * dp]     = acc[2 * q] * f;
            dst[(j0 + q) * ND + 2 * dp + 1] = acc[2 * q + 1] * f;
        }
    }
}

// =============================================================================
// K4: fused routing pass.  lane = j, permuted u layout, ur kept in registers
// (loaded ONCE per p), 4-way-split agreement chain, NO register cap, 128-thread
// CTAs so the reg file quantizes to more warps/SM.
//   MODE==1: bij_prev = 0, writes bij = agreement.
//   MODE==2: a = bij_prev + agreement.
// grid (RCTAB, NB) = (64,16), 128 threads = 4 warps; warp handles PW=4 p.
// CTA reduces its 4 warp partials in smem -> one spart slot per CTA.
// =============================================================================
template <int MODE>
__global__ __launch_bounds__(128) void k_route(int which_vj) {
    __shared__ float vj_s[NJ * ND];  // 8 KB permuted
    __shared__ float red[NJ * ND];   // 8 KB CTA partial
    const float* vj_in = (which_vj == 0) ? g_vj0 : g_vj1;
    const int b = blockIdx.y;
    const int t = threadIdx.x;
    {
        const float4* src = (const float4*)(vj_in + (size_t)b * NJ * ND) + t * 4;
        float4 v0 = src[0], v1 = src[1], v2 = src[2], v3 = src[3];
        *(float4*)(vj_s + t * 16)      = v0;
        *(float4*)(vj_s + t * 16 + 4)  = v1;
        *(float4*)(vj_s + t * 16 + 8)  = v2;
        *(float4*)(vj_s + t * 16 + 12) = v3;
#pragma unroll
        for (int k = 0; k < 16; k++) red[t * 16 + k] = 0.f;
    }
    __syncthreads();

    const int warp = t >> 5, jj = t & 31;

    unsigned long long sacc[32];
#pragma unroll
    for (int i = 0; i < 32; i++) sacc[i] = 0ull;

#pragma unroll 1
    for (int pi = 0; pi < PW; pi++) {
        const int p = (blockIdx.x * 4 + warp) * PW + pi;
        const __half* ubase = g_u + ((size_t)b * NP + p) * (NJ * ND) + jj * 2;

        // load this lane's capsule row once (32 x 128B warp lines)
        __half2 ur[32];
#pragma unroll
        for (int dp = 0; dp < 32; dp++)
            ur[dp] = *(const __half2*)(ubase + (size_t)dp * (NJ * 2));

        // agreement: 4 independent f32x2 chains
        unsigned long long ag0 = 0ull, ag1 = 0ull, ag2 = 0ull, ag3 = 0ull;
#pragma unroll
        for (int dp = 0; dp < 32; dp += 4) {
            float2 u0 = __half22float2(ur[dp]);
            float2 u1 = __half22float2(ur[dp + 1]);
            float2 u2 = __half22float2(ur[dp + 2]);
            float2 u3 = __half22float2(ur[dp + 3]);
            ffma2(ag0, pack2(u0.x, u0.y), *(const unsigned long long*)(vj_s + (dp    ) * 64 + jj * 2));
            ffma2(ag1, pack2(u1.x, u1.y), *(const unsigned long long*)(vj_s + (dp + 1) * 64 + jj * 2));
            ffma2(ag2, pack2(u2.x, u2.y), *(const unsigned long long*)(vj_s + (dp + 2) * 64 + jj * 2));
            ffma2(ag3, pack2(u3.x, u3.y), *(const unsigned long long*)(vj_s + (dp + 3) * 64 + jj * 2));
        }
        float2 f0 = unpack2(ag0), f1 = unpack2(ag1), f2 = unpack2(ag2), f3 = unpack2(ag3);
        float a = (f0.x + f0.y) + (f1.x + f1.y) + (f2.x + f2.y) + (f3.x + f3.y);

        const size_t bij_off = ((size_t)b * NP + p) * NJ + jj;
        if (MODE == 2) a += g_bij[bij_off];
        else           g_bij[bij_off] = a;

        // softmax across lanes (j)
        float m = a;
#pragma unroll
        for (int off = 16; off; off >>= 1) m = fmaxf(m, __shfl_xor_sync(0xffffffffu, m, off));
        float e = __expf(a - m);
        float s = e;
#pragma unroll
        for (int off = 16; off; off >>= 1) s += __shfl_xor_sync(0xffffffffu, s, off);
        float c = e / s;

        // accumulate c*u from registers
        unsigned long long cp = pack2(c, c);
#pragma unroll
        for (int dp = 0; dp < 32; dp++) {
            float2 uf = __half22float2(ur[dp]);
            ffma2(sacc[dp], cp, pack2(uf.x, uf.y));
        }
    }

    // CTA reduce across 4 warps (smem float atomics, addresses fully spread)
#pragma unroll
    for (int dp = 0; dp < 32; dp++) {
        float2 v = unpack2(sacc[dp]);
        atomicAdd(&red[dp * (NJ * 2) + jj * 2],     v.x);
        atomicAdd(&red[dp * (NJ * 2) + jj * 2 + 1], v.y);
    }
    __syncthreads();

    float* dst = g_spart + ((size_t)b * SLOTS + blockIdx.x) * (NJ * ND) + (size_t)t * 16;
#pragma unroll
    for (int k = 0; k < 4; k++)
        *(float4*)(dst + 4 * k) = *(const float4*)(red + t * 16 + 4 * k);
}

// =============================================================================
extern "C" void kernel_launch(void* const* d_in, const int* in_sizes, int n_in,
                              void* d_out, int out_size) {
    const float* inp  = (const float*)d_in[0];
    const float* W    = (const float*)d_in[1];
    const float* bias = (const float*)d_in[2];
    float* out = (float*)d_out;

    const int k1_smem_bytes = (2 * JG * EC * ND + NE * NB) * (int)sizeof(float);  // 69632
    cudaFuncSetAttribute(k_gemm, cudaFuncAttributeMaxDynamicSharedMemorySize, k1_smem_bytes);

    // u = inp @ W + b   (fp16, permuted, coalesced store)
    k_gemm<<<dim3(NP, 4), 128, k1_smem_bytes>>>(inp, W, bias);
    // iteration 0: uniform c -> plain p-sum (64 partials), squash -> vj0
    k_psum<<<dim3(64, NB), 256>>>();
    k_squash<<<NB, 256>>>(1.0f / 32.0f, 0, out);
    // iteration 1
    k_route<1><<<dim3(RCTAB, NB), 128>>>(0);
    k_squash<<<NB, 256>>>(1.0f, 1, out);
    // iteration 2
    k_route<2><<<dim3(RCTAB, NB), 128>>>(1);
    k_squash<<<NB, 256>>>(1.0f, 2, out);
}

// round 6
// speedup vs baseline: 1.0929x; 1.0929x over previous
#include <cuda_runtime.h>
#include <cuda_fp16.h>
#include <cstdint>

// Problem constants
#define NB 16     // batch
#define NP 1024   // primary caps
#define NJ 32     // out caps
#define NE 64     // Dp (contraction)
#define ND 64     // D

// K1 tiling
#define JG 8      // j's per CTA
#define EC 8      // e-chunk for cp.async pipeline (8 chunks, 4 buffers)
#define NCHUNK (NE / EC)          // 8
#define CHUNK_FLOATS (JG * EC * ND)  // 4096 floats = 16 KB

// Route tiling: 256-thread CTAs (8 warps = 4 warp-pairs); a PAIR handles 8 p.
#define RCTAB 32  // route CTAs per b: 32 CTAs * 4 pairs * 8 p = 1024
#define PWR 8     // p per warp-pair

#define SLOTS 64  // spart slots per b (psum uses 64, route uses RCTAB=32)

// u inner-block (2048 elems per (b,p)) is PERMUTED: index(dp,j,par) = dp*64 + j*2 + par
// where d = 2*dp + par.  g_vj0/g_vj1/g_spart use the same permuted layout.

// ---------------- scratch ----------------------------------------------------
__device__ __half g_u[(size_t)NB * NP * NJ * ND];        // 67 MB fp16, permuted
__device__ float g_spart[(size_t)NB * SLOTS * NJ * ND];  // 8.4 MB partials, permuted
__device__ float g_vj0[NB * NJ * ND];                    // permuted
__device__ float g_vj1[NB * NJ * ND];                    // permuted
__device__ float g_bij[NB * NP * NJ];

// ---------------- f32x2 helpers ---------------------------------------------
__device__ __forceinline__ unsigned long long pack2(float x, float y) {
    unsigned long long r;
    asm("mov.b64 %0, {%1,%2};" : "=l"(r) : "f"(x), "f"(y));
    return r;
}
__device__ __forceinline__ float2 unpack2(unsigned long long v) {
    float2 r;
    asm("mov.b64 {%0,%1}, %2;" : "=f"(r.x), "=f"(r.y) : "l"(v));
    return r;
}
__device__ __forceinline__ void ffma2(unsigned long long& acc,
                                      unsigned long long a, unsigned long long b) {
    asm("fma.rn.f32x2 %0, %1, %2, %0;" : "+l"(acc) : "l"(a), "l"(b));
}
__device__ __forceinline__ void cpasync16(void* dst, const void* src) {
    uint32_t s = (uint32_t)__cvta_generic_to_shared(dst);
    asm volatile("cp.async.cg.shared.global [%0], [%1], 16;" :: "r"(s), "l"(src));
}

// =============================================================================
// K1: u[b,p,j,d] = sum_e inp[b,p,e] * W[p,j,e,d] + bias[p,j,d]
// 4-deep cp.async pipeline (EC=8), fp16 PERMUTED store via smem staging.
// =============================================================================
extern __shared__ float k1_smem[];

__global__ __launch_bounds__(128, 3) void k_gemm(const float* __restrict__ inp,
                                                 const float* __restrict__ W,
                                                 const float* __restrict__ bias) {
    float* Ws    = k1_smem;                          // [4][JG][EC][ND] = 64 KB
    float* inp_t = k1_smem + 4 * CHUNK_FLOATS;       // [NE][NB], 4 KB

    const int p   = blockIdx.x;
    const int jg  = blockIdx.y;
    const int tid = threadIdx.x;

    {
        int b = tid >> 3, e0 = (tid & 7) << 3;
        const float4* src = (const float4*)(inp + ((size_t)b * NP + p) * NE + e0);
        float4 v0 = src[0], v1 = src[1];
        float v[8] = {v0.x, v0.y, v0.z, v0.w, v1.x, v1.y, v1.z, v1.w};
#pragma unroll
        for (int k = 0; k < 8; k++) inp_t[(e0 + k) * NB + b] = v[k];
    }

    const float* Wbase = W + ((size_t)p * NJ + (size_t)jg * JG) * NE * ND;

    auto prefetch = [&](int c, int buf) {
        // one chunk = 4096 floats = 1024 float4; 8 per thread
#pragma unroll
        for (int i = 0; i < 8; i++) {
            int ft  = i * 128 + tid;
            int j   = ft >> 7;
            int rem = ft & 127;
            int el  = rem >> 4;
            int d4  = rem & 15;
            const float* src = Wbase + ((size_t)j * NE + (c * EC + el)) * ND + d4 * 4;
            float* dst = Ws + (size_t)buf * CHUNK_FLOATS + ((size_t)j * EC + el) * ND + d4 * 4;
            cpasync16(dst, src);
        }
        asm volatile("cp.async.commit_group;");
    };

    prefetch(0, 0);
    prefetch(1, 1);
    prefetch(2, 2);
    __syncthreads();  // inp_t ready

    const int jl = tid >> 4;
    const int r  = tid & 15;
    const int b0 = (r & 1) << 3;
    const int d0 = (r >> 1) << 3;

    unsigned long long acc[8][4];
#pragma unroll
    for (int i = 0; i < 8; i++)
#pragma unroll
        for (int k = 0; k < 4; k++) acc[i][k] = 0ull;

    auto compute = [&](int c) {
        const float* wrow = Ws + (size_t)(c & 3) * CHUNK_FLOATS + ((size_t)jl * EC) * ND + d0;
        const float* irow = inp_t + (size_t)(c * EC) * NB + b0;
#pragma unroll
        for (int el = 0; el < EC; el++) {
            const ulonglong2* wp = (const ulonglong2*)(wrow + (size_t)el * ND);
            ulonglong2 w0 = wp[0], w1 = wp[1];
            float4 i0 = *(const float4*)(irow + (size_t)el * NB);
            float4 i1 = *(const float4*)(irow + (size_t)el * NB + 4);
            float ia[8] = {i0.x, i0.y, i0.z, i0.w, i1.x, i1.y, i1.z, i1.w};
#pragma unroll
            for (int bi = 0; bi < 8; bi++) {
                unsigned long long av = pack2(ia[bi], ia[bi]);
                ffma2(acc[bi][0], av, w0.x);
                ffma2(acc[bi][1], av, w0.y);
                ffma2(acc[bi][2], av, w1.x);
                ffma2(acc[bi][3], av, w1.y);
            }
        }
    };

    // main loop: chunks 0..4 (prefetch keeps 3 in flight)
#pragma unroll 1
    for (int c = 0; c < 5; c++) {
        asm volatile("cp.async.wait_group 2;");
        __syncthreads();
        compute(c);
        prefetch(c + 3, (c + 3) & 3);
    }
    // tail: chunks 5,6,7
    asm volatile("cp.async.wait_group 2;");
    __syncthreads();
    compute(5);
    asm volatile("cp.async.wait_group 1;");
    __syncthreads();
    compute(6);
    asm volatile("cp.async.wait_group 0;");
    __syncthreads();
    compute(7);
    __syncthreads();   // everyone done reading Ws -> reuse smem for staging

    // ---- stage fp16 tile: stage_h2[(b*32 + dp)*8 + jl] ----
    __half2* stage = (__half2*)k1_smem;   // 16 KB
    const int dp0 = d0 >> 1;
    const float* bptr = bias + ((size_t)p * NJ + (jg * JG + jl)) * ND + d0;
    float4 bb0 = *(const float4*)(bptr);
    float4 bb1 = *(const float4*)(bptr + 4);
    float bb[8] = {bb0.x, bb0.y, bb0.z, bb0.w, bb1.x, bb1.y, bb1.z, bb1.w};
#pragma unroll
    for (int bi = 0; bi < 8; bi++) {
        float2 v0 = unpack2(acc[bi][0]);
        float2 v1 = unpack2(acc[bi][1]);
        float2 v2 = unpack2(acc[bi][2]);
        float2 v3 = unpack2(acc[bi][3]);
        float fv[8] = {v0.x, v0.y, v1.x, v1.y, v2.x, v2.y, v3.x, v3.y};
        const int b = b0 + bi;
#pragma unroll
        for (int k = 0; k < 4; k++) {
            stage[((b * 32) + (dp0 + k)) * 8 + jl] =
                __floats2half2_rn(fv[2 * k] + bb[2 * k], fv[2 * k + 1] + bb[2 * k + 1]);
        }
    }
    __syncthreads();

    // ---- coalesced permuted store: 1024 float4 chunks, 8 per thread ----
#pragma unroll
    for (int i = 0; i < 8; i++) {
        int idx = i * 128 + tid;
        int b   = idx >> 6;
        int dp  = (idx & 63) >> 1;
        int sel = idx & 1;
        float4 v = *(const float4*)(stage + ((b * 32) + dp) * 8 + sel * 4);
        __half* gdst = g_u + ((size_t)b * NP + p) * (NJ * ND)
                           + (size_t)dp * (NJ * 2) + jg * 16 + sel * 8;
        *(float4*)gdst = v;
    }
}

// =============================================================================
// K2: partial sum over p for iteration 0 (uniform c).  Layout-agnostic.
// =============================================================================
__global__ void k_psum() {
    int ch = blockIdx.x;   // 64 chunks of 16 p
    int b  = blockIdx.y;
    int t  = threadIdx.x;  // 256, 8 elems each
    float acc[8];
#pragma unroll
    for (int k = 0; k < 8; k++) acc[k] = 0.f;
    size_t base = (((size_t)b * NP) + (size_t)ch * 16) * (NJ * ND) + (size_t)t * 8;
#pragma unroll
    for (int pi = 0; pi < 16; pi++) {
        uint4 raw = *(const uint4*)(g_u + base + (size_t)pi * (NJ * ND));
        const __half2* h = (const __half2*)&raw;
#pragma unroll
        for (int k = 0; k < 4; k++) {
            float2 f = __half22float2(h[k]);
            acc[2 * k]     += f.x;
            acc[2 * k + 1] += f.y;
        }
    }
    float* dst = g_spart + ((size_t)b * SLOTS + ch) * (NJ * ND) + (size_t)t * 8;
    *(float4*)dst       = make_float4(acc[0], acc[1], acc[2], acc[3]);
    *(float4*)(dst + 4) = make_float4(acc[4], acc[5], acc[6], acc[7]);
}

// =============================================================================
// K3: reduce npart partials + squash.  grid(NB), 256 threads.
// =============================================================================
__global__ void k_squash(float scale, int which, int npart, float* __restrict__ outext) {
    __shared__ float s2s[NJ];
    int b = blockIdx.x, t = threadIdx.x;
    float acc[8];
#pragma unroll
    for (int k = 0; k < 8; k++) acc[k] = 0.f;
    size_t base = (size_t)b * SLOTS * (NJ * ND) + (size_t)t * 8;
#pragma unroll 4
    for (int k = 0; k < npart; k++) {
        const float4* r4 = (const float4*)(g_spart + base + (size_t)k * (NJ * ND));
        float4 v0 = r4[0], v1 = r4[1];
        acc[0] += v0.x; acc[1] += v0.y; acc[2] += v0.z; acc[3] += v0.w;
        acc[4] += v1.x; acc[5] += v1.y; acc[6] += v1.z; acc[7] += v1.w;
    }
#pragma unroll
    for (int k = 0; k < 8; k++) acc[k] *= scale;

    if (t < NJ) s2s[t] = 0.f;
    __syncthreads();
    int dp = t >> 3;
    int j0 = (t & 7) * 4;
#pragma unroll
    for (int q = 0; q < 4; q++)
        atomicAdd(&s2s[j0 + q], acc[2 * q] * acc[2 * q] + acc[2 * q + 1] * acc[2 * q + 1]);
    __syncthreads();

    if (which < 2) {
        float* out = (which == 0) ? g_vj0 : g_vj1;
        float* dst = out + (size_t)b * (NJ * ND) + (size_t)t * 8;
#pragma unroll
        for (int q = 0; q < 4; q++) {
            float s2 = s2s[j0 + q];
            float f = sqrtf(s2) / (1.0f + s2);
            dst[2 * q]     = acc[2 * q] * f;
            dst[2 * q + 1] = acc[2 * q + 1] * f;
        }
    } else {
        float* dst = outext + (size_t)b * (NJ * ND);
#pragma unroll
        for (int q = 0; q < 4; q++) {
            float s2 = s2s[j0 + q];
            float f = sqrtf(s2) / (1.0f + s2);
            dst[(j0 + q) * ND + 2 * dp]     = acc[2 * q] * f;
            dst[(j0 + q) * ND + 2 * dp + 1] = acc[2 * q + 1] * f;
        }
    }
}

// =============================================================================
// K4: fused routing pass, WARP-PAIR version.  lane = j; warp parity = dp-half.
// Each warp holds only 16 dp: ur[16] + sacc[16] -> ~80 live regs (no cap!).
// Partial agreement dots exchanged via double-buffered smem; one __syncthreads
// per p.  CTA reduces 8 warp partials into red[] -> one spart slot per CTA.
//   MODE==1: bij_prev = 0, writes bij = agreement.
//   MODE==2: a = bij_prev + agreement.
// grid (RCTAB, NB) = (32,16), 256 threads; warp-pair handles PWR=8 p.
// =============================================================================
template <int MODE>
__global__ __launch_bounds__(256) void k_route(int which_vj) {
    __shared__ float vj_s[NJ * ND];          // 8 KB permuted
    __shared__ float red[NJ * ND];           // 8 KB CTA partial
    __shared__ float pairbuf[2][4][2][NJ];   // [pi&1][pair][half][j], 2 KB
    const float* vj_in = (which_vj == 0) ? g_vj0 : g_vj1;
    const int b = blockIdx.y;
    const int t = threadIdx.x;
    {
        const float4* src = (const float4*)(vj_in + (size_t)b * NJ * ND) + t * 2;
        float4 v0 = src[0], v1 = src[1];
        *(float4*)(vj_s + t * 8)     = v0;
        *(float4*)(vj_s + t * 8 + 4) = v1;
#pragma unroll
        for (int k = 0; k < 8; k++) red[t * 8 + k] = 0.f;
    }
    __syncthreads();

    const int warp = t >> 5, jj = t & 31;
    const int pair = warp >> 1, half = warp & 1;

    unsigned long long sacc[16];
#pragma unroll
    for (int i = 0; i < 16; i++) sacc[i] = 0ull;

#pragma unroll 1
    for (int pi = 0; pi < PWR; pi++) {
        const int p = (blockIdx.x * 4 + pair) * PWR + pi;
        const __half* ubase = g_u + ((size_t)b * NP + p) * (NJ * ND)
                                  + (size_t)half * 16 * (NJ * 2) + jj * 2;

        // load this warp's dp-half of the capsule row (16 x 128B lines)
        __half2 ur[16];
#pragma unroll
        for (int dpl = 0; dpl < 16; dpl++)
            ur[dpl] = *(const __half2*)(ubase + (size_t)dpl * (NJ * 2));

        // partial agreement over this half: 2 independent f32x2 chains
        const float* vrow = vj_s + (half * 16) * (NJ * 2) + jj * 2;
        unsigned long long ag0 = 0ull, ag1 = 0ull;
#pragma unroll
        for (int dpl = 0; dpl < 16; dpl += 2) {
            float2 u0 = __half22float2(ur[dpl]);
            float2 u1 = __half22float2(ur[dpl + 1]);
            ffma2(ag0, pack2(u0.x, u0.y), *(const unsigned long long*)(vrow + (dpl    ) * (NJ * 2)));
            ffma2(ag1, pack2(u1.x, u1.y), *(const unsigned long long*)(vrow + (dpl + 1) * (NJ * 2)));
        }
        float2 f0 = unpack2(ag0), f1 = unpack2(ag1);
        pairbuf[pi & 1][pair][half][jj] = (f0.x + f0.y) + (f1.x + f1.y);
        __syncthreads();

        float a = pairbuf[pi & 1][pair][0][jj] + pairbuf[pi & 1][pair][1][jj];
        const size_t bij_off = ((size_t)b * NP + p) * NJ + jj;
        if (MODE == 2) a += g_bij[bij_off];
        else if (half == 0) g_bij[bij_off] = a;

        // softmax across lanes (j); both warps compute identical values
        float m = a;
#pragma unroll
        for (int off = 16; off; off >>= 1) m = fmaxf(m, __shfl_xor_sync(0xffffffffu, m, off));
        float e = __expf(a - m);
        float s = e;
#pragma unroll
        for (int off = 16; off; off >>= 1) s += __shfl_xor_sync(0xffffffffu, s, off);
        float c = e / s;

        // accumulate c*u for this dp-half
        unsigned long long cp = pack2(c, c);
#pragma unroll
        for (int dpl = 0; dpl < 16; dpl++) {
            float2 uf = __half22float2(ur[dpl]);
            ffma2(sacc[dpl], cp, pack2(uf.x, uf.y));
        }
    }

    // CTA reduce: each warp adds its dp-half (4 pairs collide -> atomics)
#pragma unroll
    for (int dpl = 0; dpl < 16; dpl++) {
        float2 v = unpack2(sacc[dpl]);
        int off = (half * 16 + dpl) * (NJ * 2) + jj * 2;
        atomicAdd(&red[off],     v.x);
        atomicAdd(&red[off + 1], v.y);
    }
    __syncthreads();

    // one slot per CTA (route uses slots 0..RCTAB-1)
    float* dst = g_spart + ((size_t)b * SLOTS + blockIdx.x) * (NJ * ND) + (size_t)t * 8;
    *(float4*)dst       = *(const float4*)(red + t * 8);
    *(float4*)(dst + 4) = *(const float4*)(red + t * 8 + 4);
}

// =============================================================================
extern "C" void kernel_launch(void* const* d_in, const int* in_sizes, int n_in,
                              void* d_out, int out_size) {
    const float* inp  = (const float*)d_in[0];
    const float* W    = (const float*)d_in[1];
    const float* bias = (const float*)d_in[2];
    float* out = (float*)d_out;

    const int k1_smem_bytes = (4 * CHUNK_FLOATS + NE * NB) * (int)sizeof(float);  // 69632
    cudaFuncSetAttribute(k_gemm, cudaFuncAttributeMaxDynamicSharedMemorySize, k1_smem_bytes);

    // u = inp @ W + b   (fp16, permuted, coalesced store, 4-deep pipeline)
    k_gemm<<<dim3(NP, 4), 128, k1_smem_bytes>>>(inp, W, bias);
    // iteration 0: uniform c -> plain p-sum (64 partials), squash -> vj0
    k_psum<<<dim3(64, NB), 256>>>();
    k_squash<<<NB, 256>>>(1.0f / 32.0f, 0, 64, out);
    // iteration 1
    k_route<1><<<dim3(RCTAB, NB), 256>>>(0);
    k_squash<<<NB, 256>>>(1.0f, 1, RCTAB, out);
    // iteration 2
    k_route<2><<<dim3(RCTAB, NB), 256>>>(1);
    k_squash<<<NB, 256>>>(1.0f, 2, RCTAB, out);
}

// round 7
// speedup vs baseline: 1.1422x; 1.0451x over previous
#include <cuda_runtime.h>
#include <cuda_fp16.h>
#include <cstdint>

// Problem constants
#define NB 16     // batch
#define NP 1024   // primary caps
#define NJ 32     // out caps
#define NE 64     // Dp (contraction)
#define ND 64     // D

// K1 tiling
#define JG 8      // j's per CTA
#define EC 8      // e-chunk for cp.async pipeline (8 chunks, 4 buffers)
#define CHUNK_FLOATS (JG * EC * ND)  // 4096 floats = 16 KB

// Route tiling: 256-thread CTAs (8 warps = 4 warp-pairs); a PAIR handles 8 p.
#define RCTAB 32  // route CTAs per b: 32 CTAs * 4 pairs * 8 p = 1024
#define PWR 8     // p per warp-pair

#define SLOTS 64  // spart slots per b (psum uses 64, route uses RCTAB=32)

// u inner-block (2048 elems per (b,p)) is PERMUTED: index(dp,j,par) = dp*64 + j*2 + par
// where d = 2*dp + par.  g_vj0/g_vj1/g_spart use the same permuted layout.

// ---------------- scratch ----------------------------------------------------
__device__ __half g_u[(size_t)NB * NP * NJ * ND];        // 67 MB fp16, permuted
__device__ float g_spart[(size_t)NB * SLOTS * NJ * ND];  // 8.4 MB partials, permuted
__device__ float g_vj0[NB * NJ * ND];                    // permuted
__device__ float g_vj1[NB * NJ * ND];                    // permuted
__device__ float g_bij[NB * NP * NJ];

// ---------------- f32x2 helpers ---------------------------------------------
__device__ __forceinline__ unsigned long long pack2(float x, float y) {
    unsigned long long r;
    asm("mov.b64 %0, {%1,%2};" : "=l"(r) : "f"(x), "f"(y));
    return r;
}
__device__ __forceinline__ float2 unpack2(unsigned long long v) {
    float2 r;
    asm("mov.b64 {%0,%1}, %2;" : "=f"(r.x), "=f"(r.y) : "l"(v));
    return r;
}
__device__ __forceinline__ void ffma2(unsigned long long& acc,
                                      unsigned long long a, unsigned long long b) {
    asm("fma.rn.f32x2 %0, %1, %2, %0;" : "+l"(acc) : "l"(a), "l"(b));
}
__device__ __forceinline__ void cpasync16(void* dst, const void* src) {
    uint32_t s = (uint32_t)__cvta_generic_to_shared(dst);
    asm volatile("cp.async.cg.shared.global [%0], [%1], 16;" :: "r"(s), "l"(src));
}

// =============================================================================
// K1: u[b,p,j,d] = sum_e inp[b,p,e] * W[p,j,e,d] + bias[p,j,d]
// 4-deep cp.async pipeline (EC=8), fp16 PERMUTED store via smem staging.
// (unchanged from R6)
// =============================================================================
extern __shared__ float k1_smem[];

__global__ __launch_bounds__(128, 3) void k_gemm(const float* __restrict__ inp,
                                                 const float* __restrict__ W,
                                                 const float* __restrict__ bias) {
    float* Ws    = k1_smem;                          // [4][JG][EC][ND] = 64 KB
    float* inp_t = k1_smem + 4 * CHUNK_FLOATS;       // [NE][NB], 4 KB

    const int p   = blockIdx.x;
    const int jg  = blockIdx.y;
    const int tid = threadIdx.x;

    {
        int b = tid >> 3, e0 = (tid & 7) << 3;
        const float4* src = (const float4*)(inp + ((size_t)b * NP + p) * NE + e0);
        float4 v0 = src[0], v1 = src[1];
        float v[8] = {v0.x, v0.y, v0.z, v0.w, v1.x, v1.y, v1.z, v1.w};
#pragma unroll
        for (int k = 0; k < 8; k++) inp_t[(e0 + k) * NB + b] = v[k];
    }

    const float* Wbase = W + ((size_t)p * NJ + (size_t)jg * JG) * NE * ND;

    auto prefetch = [&](int c, int buf) {
#pragma unroll
        for (int i = 0; i < 8; i++) {
            int ft  = i * 128 + tid;
            int j   = ft >> 7;
            int rem = ft & 127;
            int el  = rem >> 4;
            int d4  = rem & 15;
            const float* src = Wbase + ((size_t)j * NE + (c * EC + el)) * ND + d4 * 4;
            float* dst = Ws + (size_t)buf * CHUNK_FLOATS + ((size_t)j * EC + el) * ND + d4 * 4;
            cpasync16(dst, src);
        }
        asm volatile("cp.async.commit_group;");
    };

    prefetch(0, 0);
    prefetch(1, 1);
    prefetch(2, 2);
    __syncthreads();  // inp_t ready

    const int jl = tid >> 4;
    const int r  = tid & 15;
    const int b0 = (r & 1) << 3;
    const int d0 = (r >> 1) << 3;

    unsigned long long acc[8][4];
#pragma unroll
    for (int i = 0; i < 8; i++)
#pragma unroll
        for (int k = 0; k < 4; k++) acc[i][k] = 0ull;

    auto compute = [&](int c) {
        const float* wrow = Ws + (size_t)(c & 3) * CHUNK_FLOATS + ((size_t)jl * EC) * ND + d0;
        const float* irow = inp_t + (size_t)(c * EC) * NB + b0;
#pragma unroll
        for (int el = 0; el < EC; el++) {
            const ulonglong2* wp = (const ulonglong2*)(wrow + (size_t)el * ND);
            ulonglong2 w0 = wp[0], w1 = wp[1];
            float4 i0 = *(const float4*)(irow + (size_t)el * NB);
            float4 i1 = *(const float4*)(irow + (size_t)el * NB + 4);
            float ia[8] = {i0.x, i0.y, i0.z, i0.w, i1.x, i1.y, i1.z, i1.w};
#pragma unroll
            for (int bi = 0; bi < 8; bi++) {
                unsigned long long av = pack2(ia[bi], ia[bi]);
                ffma2(acc[bi][0], av, w0.x);
                ffma2(acc[bi][1], av, w0.y);
                ffma2(acc[bi][2], av, w1.x);
                ffma2(acc[bi][3], av, w1.y);
            }
        }
    };

#pragma unroll 1
    for (int c = 0; c < 5; c++) {
        asm volatile("cp.async.wait_group 2;");
        __syncthreads();
        compute(c);
        prefetch(c + 3, (c + 3) & 3);
    }
    asm volatile("cp.async.wait_group 2;");
    __syncthreads();
    compute(5);
    asm volatile("cp.async.wait_group 1;");
    __syncthreads();
    compute(6);
    asm volatile("cp.async.wait_group 0;");
    __syncthreads();
    compute(7);
    __syncthreads();   // done reading Ws -> reuse smem for staging

    // ---- stage fp16 tile: stage_h2[(b*32 + dp)*8 + jl] ----
    __half2* stage = (__half2*)k1_smem;   // 16 KB
    const int dp0 = d0 >> 1;
    const float* bptr = bias + ((size_t)p * NJ + (jg * JG + jl)) * ND + d0;
    float4 bb0 = *(const float4*)(bptr);
    float4 bb1 = *(const float4*)(bptr + 4);
    float bb[8] = {bb0.x, bb0.y, bb0.z, bb0.w, bb1.x, bb1.y, bb1.z, bb1.w};
#pragma unroll
    for (int bi = 0; bi < 8; bi++) {
        float2 v0 = unpack2(acc[bi][0]);
        float2 v1 = unpack2(acc[bi][1]);
        float2 v2 = unpack2(acc[bi][2]);
        float2 v3 = unpack2(acc[bi][3]);
        float fv[8] = {v0.x, v0.y, v1.x, v1.y, v2.x, v2.y, v3.x, v3.y};
        const int b = b0 + bi;
#pragma unroll
        for (int k = 0; k < 4; k++) {
            stage[((b * 32) + (dp0 + k)) * 8 + jl] =
                __floats2half2_rn(fv[2 * k] + bb[2 * k], fv[2 * k + 1] + bb[2 * k + 1]);
        }
    }
    __syncthreads();

#pragma unroll
    for (int i = 0; i < 8; i++) {
        int idx = i * 128 + tid;
        int b   = idx >> 6;
        int dp  = (idx & 63) >> 1;
        int sel = idx & 1;
        float4 v = *(const float4*)(stage + ((b * 32) + dp) * 8 + sel * 4);
        __half* gdst = g_u + ((size_t)b * NP + p) * (NJ * ND)
                           + (size_t)dp * (NJ * 2) + jg * 16 + sel * 8;
        *(float4*)gdst = v;
    }
}

// =============================================================================
// K2: partial sum over p for iteration 0 (uniform c).  (unchanged)
// =============================================================================
__global__ void k_psum() {
    int ch = blockIdx.x;
    int b  = blockIdx.y;
    int t  = threadIdx.x;
    float acc[8];
#pragma unroll
    for (int k = 0; k < 8; k++) acc[k] = 0.f;
    size_t base = (((size_t)b * NP) + (size_t)ch * 16) * (NJ * ND) + (size_t)t * 8;
#pragma unroll
    for (int pi = 0; pi < 16; pi++) {
        uint4 raw = *(const uint4*)(g_u + base + (size_t)pi * (NJ * ND));
        const __half2* h = (const __half2*)&raw;
#pragma unroll
        for (int k = 0; k < 4; k++) {
            float2 f = __half22float2(h[k]);
            acc[2 * k]     += f.x;
            acc[2 * k + 1] += f.y;
        }
    }
    float* dst = g_spart + ((size_t)b * SLOTS + ch) * (NJ * ND) + (size_t)t * 8;
    *(float4*)dst       = make_float4(acc[0], acc[1], acc[2], acc[3]);
    *(float4*)(dst + 4) = make_float4(acc[4], acc[5], acc[6], acc[7]);
}

// =============================================================================
// K3: reduce npart partials + squash.  (unchanged)
// =============================================================================
__global__ void k_squash(float scale, int which, int npart, float* __restrict__ outext) {
    __shared__ float s2s[NJ];
    int b = blockIdx.x, t = threadIdx.x;
    float acc[8];
#pragma unroll
    for (int k = 0; k < 8; k++) acc[k] = 0.f;
    size_t base = (size_t)b * SLOTS * (NJ * ND) + (size_t)t * 8;
#pragma unroll 4
    for (int k = 0; k < npart; k++) {
        const float4* r4 = (const float4*)(g_spart + base + (size_t)k * (NJ * ND));
        float4 v0 = r4[0], v1 = r4[1];
        acc[0] += v0.x; acc[1] += v0.y; acc[2] += v0.z; acc[3] += v0.w;
        acc[4] += v1.x; acc[5] += v1.y; acc[6] += v1.z; acc[7] += v1.w;
    }
#pragma unroll
    for (int k = 0; k < 8; k++) acc[k] *= scale;

    if (t < NJ) s2s[t] = 0.f;
    __syncthreads();
    int dp = t >> 3;
    int j0 = (t & 7) * 4;
#pragma unroll
    for (int q = 0; q < 4; q++)
        atomicAdd(&s2s[j0 + q], acc[2 * q] * acc[2 * q] + acc[2 * q + 1] * acc[2 * q + 1]);
    __syncthreads();

    if (which < 2) {
        float* out = (which == 0) ? g_vj0 : g_vj1;
        float* dst = out + (size_t)b * (NJ * ND) + (size_t)t * 8;
#pragma unroll
        for (int q = 0; q < 4; q++) {
            float s2 = s2s[j0 + q];
            float f = sqrtf(s2) / (1.0f + s2);
            dst[2 * q]     = acc[2 * q] * f;
            dst[2 * q + 1] = acc[2 * q + 1] * f;
        }
    } else {
        float* dst = outext + (size_t)b * (NJ * ND);
#pragma unroll
        for (int q = 0; q < 4; q++) {
            float s2 = s2s[j0 + q];
            float f = sqrtf(s2) / (1.0f + s2);
            dst[(j0 + q) * ND + 2 * dp]     = acc[2 * q] * f;
            dst[(j0 + q) * ND + 2 * dp + 1] = acc[2 * q + 1] * f;
        }
    }
}

// =============================================================================
// K4: fused routing pass v3.  Warp-pair (lane=j, warp parity = dp-half) with:
//   - register double-buffer prefetch of next p's u row (loads overlap compute)
//   - PAIR-LOCAL named barrier (bar.sync pair, 64) instead of __syncthreads
//   - softmax without max-subtraction (|logit| <= ~10 -> fp32-safe)
// grid (RCTAB, NB) = (32,16), 256 threads; pair handles PWR=8 p.
// =============================================================================
template <int MODE>
__global__ __launch_bounds__(256) void k_route(int which_vj) {
    __shared__ float vj_s[NJ * ND];          // 8 KB permuted
    __shared__ float red[NJ * ND];           // 8 KB CTA partial
    __shared__ float pairbuf[2][4][2][NJ];   // [pi&1][pair][half][j]
    const float* vj_in = (which_vj == 0) ? g_vj0 : g_vj1;
    const int b = blockIdx.y;
    const int t = threadIdx.x;
    {
        const float4* src = (const float4*)(vj_in + (size_t)b * NJ * ND) + t * 2;
        float4 v0 = src[0], v1 = src[1];
        *(float4*)(vj_s + t * 8)     = v0;
        *(float4*)(vj_s + t * 8 + 4) = v1;
#pragma unroll
        for (int k = 0; k < 8; k++) red[t * 8 + k] = 0.f;
    }
    __syncthreads();

    const int warp = t >> 5, jj = t & 31;
    const int pair = warp >> 1, half = warp & 1;
    const int barid = pair + 1;  // named barriers 1..4 (0 = __syncthreads)

    unsigned long long sacc[16];
#pragma unroll
    for (int i = 0; i < 16; i++) sacc[i] = 0ull;

    const int pbase = (blockIdx.x * 4 + pair) * PWR;
    const __half* ubase = g_u + ((size_t)b * NP + pbase) * (NJ * ND)
                              + (size_t)half * 16 * (NJ * 2) + jj * 2;
    const float* vrow = vj_s + (half * 16) * (NJ * 2) + jj * 2;

    __half2 urA[16], urB[16];
#pragma unroll
    for (int dpl = 0; dpl < 16; dpl++)
        urA[dpl] = *(const __half2*)(ubase + (size_t)dpl * (NJ * 2));

    auto body = [&](int pi, __half2 (&cur)[16], __half2 (&nxt)[16]) {
        const int p = pbase + pi;
        // prefetch next p's row (overlaps everything below)
        if (pi < PWR - 1) {
            const __half* un = ubase + (size_t)(pi + 1) * (NJ * ND);
#pragma unroll
            for (int dpl = 0; dpl < 16; dpl++)
                nxt[dpl] = *(const __half2*)(un + (size_t)dpl * (NJ * 2));
        }
        const size_t bij_off = ((size_t)b * NP + p) * NJ + jj;
        float bijv = 0.f;
        if (MODE == 2) bijv = g_bij[bij_off];  // independent early load

        // partial agreement over this dp-half: 2 independent f32x2 chains
        unsigned long long ag0 = 0ull, ag1 = 0ull;
#pragma unroll
        for (int dpl = 0; dpl < 16; dpl += 2) {
            float2 u0 = __half22float2(cur[dpl]);
            float2 u1 = __half22float2(cur[dpl + 1]);
            ffma2(ag0, pack2(u0.x, u0.y), *(const unsigned long long*)(vrow + (dpl    ) * (NJ * 2)));
            ffma2(ag1, pack2(u1.x, u1.y), *(const unsigned long long*)(vrow + (dpl + 1) * (NJ * 2)));
        }
        float2 f0 = unpack2(ag0), f1 = unpack2(ag1);
        pairbuf[pi & 1][pair][half][jj] = (f0.x + f0.y) + (f1.x + f1.y);
        asm volatile("bar.sync %0, 64;" :: "r"(barid) : "memory");
        float a = pairbuf[pi & 1][pair][0][jj] + pairbuf[pi & 1][pair][1][jj] + bijv;
        if (MODE == 1 && half == 0) g_bij[bij_off] = a;

        // softmax across lanes, no max-shift (|a| <= ~10 -> exp safe in fp32)
        float e = __expf(a);
        float s = e;
#pragma unroll
        for (int off = 16; off; off >>= 1) s += __shfl_xor_sync(0xffffffffu, s, off);
        float c = e / s;

        unsigned long long cp = pack2(c, c);
#pragma unroll
        for (int dpl = 0; dpl < 16; dpl++) {
            float2 uf = __half22float2(cur[dpl]);
            ffma2(sacc[dpl], cp, pack2(uf.x, uf.y));
        }
    };

#pragma unroll
    for (int pi = 0; pi < PWR; pi++) {
        if (pi & 1) body(pi, urB, urA);
        else        body(pi, urA, urB);
    }

    // CTA reduce: each warp adds its dp-half (4 pairs collide -> smem atomics)
#pragma unroll
    for (int dpl = 0; dpl < 16; dpl++) {
        float2 v = unpack2(sacc[dpl]);
        int off = (half * 16 + dpl) * (NJ * 2) + jj * 2;
        atomicAdd(&red[off],     v.x);
        atomicAdd(&red[off + 1], v.y);
    }
    __syncthreads();

    float* dst = g_spart + ((size_t)b * SLOTS + blockIdx.x) * (NJ * ND) + (size_t)t * 8;
    *(float4*)dst       = *(const float4*)(red + t * 8);
    *(float4*)(dst + 4) = *(const float4*)(red + t * 8 + 4);
}

// =============================================================================
extern "C" void kernel_launch(void* const* d_in, const int* in_sizes, int n_in,
                              void* d_out, int out_size) {
    const float* inp  = (const float*)d_in[0];
    const float* W    = (const float*)d_in[1];
    const float* bias = (const float*)d_in[2];
    float* out = (float*)d_out;

    const int k1_smem_bytes = (4 * CHUNK_FLOATS + NE * NB) * (int)sizeof(float);  // 69632
    cudaFuncSetAttribute(k_gemm, cudaFuncAttributeMaxDynamicSharedMemorySize, k1_smem_bytes);

    // u = inp @ W + b   (fp16, permuted, coalesced store, 4-deep pipeline)
    k_gemm<<<dim3(NP, 4), 128, k1_smem_bytes>>>(inp, W, bias);
    // iteration 0: uniform c -> plain p-sum (64 partials), squash -> vj0
    k_psum<<<dim3(64, NB), 256>>>();
    k_squash<<<NB, 256>>>(1.0f / 32.0f, 0, 64, out);
    // iteration 1
    k_route<1><<<dim3(RCTAB, NB), 256>>>(0);
    k_squash<<<NB, 256>>>(1.0f, 1, RCTAB, out);
    // iteration 2
    k_route<2><<<dim3(RCTAB, NB), 256>>>(1);
    k_squash<<<NB, 256>>>(1.0f, 2, RCTAB, out);
}

// round 8
// speedup vs baseline: 1.1971x; 1.0481x over previous
#include <cuda_runtime.h>
#include <cuda_fp16.h>
#include <cstdint>

// Problem constants
#define NB 16     // batch
#define NP 1024   // primary caps
#define NJ 32     // out caps
#define NE 64     // Dp (contraction)
#define ND 64     // D

// K1 tiling
#define JG 8      // j's per CTA
#define EC 8      // e-chunk; 8 chunks, 3 smem buffers (52 KB total -> 4 CTAs/SM)
#define CHUNK_FLOATS (JG * EC * ND)  // 4096 floats = 16 KB

// Route tiling: 256-thread CTAs (8 warps = 4 warp-pairs); a PAIR handles 16 p.
// grid (16, NB) = 256 CTAs -> single resident wave at 2 CTAs/SM.
#define RCTAB 16  // route CTAs per b: 16 CTAs * 4 pairs * 16 p = 1024
#define PWR 16    // p per warp-pair

#define SLOTS 64  // spart slots per b (psum uses 64, route uses RCTAB=16)

// u inner-block (2048 elems per (b,p)) is PERMUTED: index(dp,j,par) = dp*64 + j*2 + par
// where d = 2*dp + par.  g_vj0/g_vj1/g_spart use the same permuted layout.

// ---------------- scratch ----------------------------------------------------
__device__ __half g_u[(size_t)NB * NP * NJ * ND];        // 67 MB fp16, permuted
__device__ float g_spart[(size_t)NB * SLOTS * NJ * ND];  // 8.4 MB partials, permuted
__device__ float g_vj0[NB * NJ * ND];                    // permuted
__device__ float g_vj1[NB * NJ * ND];                    // permuted
__device__ float g_bij[NB * NP * NJ];

// ---------------- f32x2 helpers ---------------------------------------------
__device__ __forceinline__ unsigned long long pack2(float x, float y) {
    unsigned long long r;
    asm("mov.b64 %0, {%1,%2};" : "=l"(r) : "f"(x), "f"(y));
    return r;
}
__device__ __forceinline__ float2 unpack2(unsigned long long v) {
    float2 r;
    asm("mov.b64 {%0,%1}, %2;" : "=f"(r.x), "=f"(r.y) : "l"(v));
    return r;
}
__device__ __forceinline__ void ffma2(unsigned long long& acc,
                                      unsigned long long a, unsigned long long b) {
    asm("fma.rn.f32x2 %0, %1, %2, %0;" : "+l"(acc) : "l"(a), "l"(b));
}
__device__ __forceinline__ void cpasync16(void* dst, const void* src) {
    uint32_t s = (uint32_t)__cvta_generic_to_shared(dst);
    asm volatile("cp.async.cg.shared.global [%0], [%1], 16;" :: "r"(s), "l"(src));
}

// =============================================================================
// K1: u[b,p,j,d] = sum_e inp[b,p,e] * W[p,j,e,d] + bias[p,j,d]
// 3-buffer cp.async pipeline (EC=8), 52 KB smem -> target 4 CTAs/SM.
// fp16 PERMUTED store via smem staging.
// =============================================================================
extern __shared__ float k1_smem[];

__global__ __launch_bounds__(128, 3) void k_gemm(const float* __restrict__ inp,
                                                 const float* __restrict__ W,
                                                 const float* __restrict__ bias) {
    float* Ws    = k1_smem;                          // [3][JG][EC][ND] = 48 KB
    float* inp_t = k1_smem + 3 * CHUNK_FLOATS;       // [NE][NB], 4 KB

    const int p   = blockIdx.x;
    const int jg  = blockIdx.y;
    const int tid = threadIdx.x;

    {
        int b = tid >> 3, e0 = (tid & 7) << 3;
        const float4* src = (const float4*)(inp + ((size_t)b * NP + p) * NE + e0);
        float4 v0 = src[0], v1 = src[1];
        float v[8] = {v0.x, v0.y, v0.z, v0.w, v1.x, v1.y, v1.z, v1.w};
#pragma unroll
        for (int k = 0; k < 8; k++) inp_t[(e0 + k) * NB + b] = v[k];
    }

    const float* Wbase = W + ((size_t)p * NJ + (size_t)jg * JG) * NE * ND;

    auto prefetch = [&](int c, int buf) {
#pragma unroll
        for (int i = 0; i < 8; i++) {
            int ft  = i * 128 + tid;
            int j   = ft >> 7;
            int rem = ft & 127;
            int el  = rem >> 4;
            int d4  = rem & 15;
            const float* src = Wbase + ((size_t)j * NE + (c * EC + el)) * ND + d4 * 4;
            float* dst = Ws + (size_t)buf * CHUNK_FLOATS + ((size_t)j * EC + el) * ND + d4 * 4;
            cpasync16(dst, src);
        }
        asm volatile("cp.async.commit_group;");
    };

    prefetch(0, 0);
    prefetch(1, 1);
    prefetch(2, 2);
    __syncthreads();  // inp_t ready

    const int jl = tid >> 4;
    const int r  = tid & 15;
    const int b0 = (r & 1) << 3;
    const int d0 = (r >> 1) << 3;

    unsigned long long acc[8][4];
#pragma unroll
    for (int i = 0; i < 8; i++)
#pragma unroll
        for (int k = 0; k < 4; k++) acc[i][k] = 0ull;

    auto compute = [&](int c) {
        const float* wrow = Ws + (size_t)(c % 3) * CHUNK_FLOATS + ((size_t)jl * EC) * ND + d0;
        const float* irow = inp_t + (size_t)(c * EC) * NB + b0;
#pragma unroll
        for (int el = 0; el < EC; el++) {
            const ulonglong2* wp = (const ulonglong2*)(wrow + (size_t)el * ND);
            ulonglong2 w0 = wp[0], w1 = wp[1];
            float4 i0 = *(const float4*)(irow + (size_t)el * NB);
            float4 i1 = *(const float4*)(irow + (size_t)el * NB + 4);
            float ia[8] = {i0.x, i0.y, i0.z, i0.w, i1.x, i1.y, i1.z, i1.w};
#pragma unroll
            for (int bi = 0; bi < 8; bi++) {
                unsigned long long av = pack2(ia[bi], ia[bi]);
                ffma2(acc[bi][0], av, w0.x);
                ffma2(acc[bi][1], av, w0.y);
                ffma2(acc[bi][2], av, w1.x);
                ffma2(acc[bi][3], av, w1.y);
            }
        }
    };

    // chunks 0..4: wait for chunk c, compute, then (after all warps done with
    // the buffer) refill it with chunk c+3
#pragma unroll 1
    for (int c = 0; c < 5; c++) {
        asm volatile("cp.async.wait_group 2;");
        __syncthreads();
        compute(c);
        __syncthreads();               // buffer c%3 free across whole CTA
        prefetch(c + 3, (c + 3) % 3);
    }
    asm volatile("cp.async.wait_group 2;");
    __syncthreads();
    compute(5);
    asm volatile("cp.async.wait_group 1;");
    __syncthreads();
    compute(6);
    asm volatile("cp.async.wait_group 0;");
    __syncthreads();
    compute(7);
    __syncthreads();   // done reading Ws -> reuse smem for staging

    // ---- stage fp16 tile: stage_h2[(b*32 + dp)*8 + jl] ----
    __half2* stage = (__half2*)k1_smem;   // 16 KB
    const int dp0 = d0 >> 1;
    const float* bptr = bias + ((size_t)p * NJ + (jg * JG + jl)) * ND + d0;
    float4 bb0 = *(const float4*)(bptr);
    float4 bb1 = *(const float4*)(bptr + 4);
    float bb[8] = {bb0.x, bb0.y, bb0.z, bb0.w, bb1.x, bb1.y, bb1.z, bb1.w};
#pragma unroll
    for (int bi = 0; bi < 8; bi++) {
        float2 v0 = unpack2(acc[bi][0]);
        float2 v1 = unpack2(acc[bi][1]);
        float2 v2 = unpack2(acc[bi][2]);
        float2 v3 = unpack2(acc[bi][3]);
        float fv[8] = {v0.x, v0.y, v1.x, v1.y, v2.x, v2.y, v3.x, v3.y};
        const int b = b0 + bi;
#pragma unroll
        for (int k = 0; k < 4; k++) {
            stage[((b * 32) + (dp0 + k)) * 8 + jl] =
                __floats2half2_rn(fv[2 * k] + bb[2 * k], fv[2 * k + 1] + bb[2 * k + 1]);
        }
    }
    __syncthreads();

#pragma unroll
    for (int i = 0; i < 8; i++) {
        int idx = i * 128 + tid;
        int b   = idx >> 6;
        int dp  = (idx & 63) >> 1;
        int sel = idx & 1;
        float4 v = *(const float4*)(stage + ((b * 32) + dp) * 8 + sel * 4);
        __half* gdst = g_u + ((size_t)b * NP + p) * (NJ * ND)
                           + (size_t)dp * (NJ * 2) + jg * 16 + sel * 8;
        *(float4*)gdst = v;
    }
}

// =============================================================================
// K2: partial sum over p for iteration 0 (uniform c).  (unchanged)
// =============================================================================
__global__ void k_psum() {
    int ch = blockIdx.x;
    int b  = blockIdx.y;
    int t  = threadIdx.x;
    float acc[8];
#pragma unroll
    for (int k = 0; k < 8; k++) acc[k] = 0.f;
    size_t base = (((size_t)b * NP) + (size_t)ch * 16) * (NJ * ND) + (size_t)t * 8;
#pragma unroll
    for (int pi = 0; pi < 16; pi++) {
        uint4 raw = *(const uint4*)(g_u + base + (size_t)pi * (NJ * ND));
        const __half2* h = (const __half2*)&raw;
#pragma unroll
        for (int k = 0; k < 4; k++) {
            float2 f = __half22float2(h[k]);
            acc[2 * k]     += f.x;
            acc[2 * k + 1] += f.y;
        }
    }
    float* dst = g_spart + ((size_t)b * SLOTS + ch) * (NJ * ND) + (size_t)t * 8;
    *(float4*)dst       = make_float4(acc[0], acc[1], acc[2], acc[3]);
    *(float4*)(dst + 4) = make_float4(acc[4], acc[5], acc[6], acc[7]);
}

// =============================================================================
// K3: reduce npart partials + squash.  (unchanged)
// =============================================================================
__global__ void k_squash(float scale, int which, int npart, float* __restrict__ outext) {
    __shared__ float s2s[NJ];
    int b = blockIdx.x, t = threadIdx.x;
    float acc[8];
#pragma unroll
    for (int k = 0; k < 8; k++) acc[k] = 0.f;
    size_t base = (size_t)b * SLOTS * (NJ * ND) + (size_t)t * 8;
#pragma unroll 4
    for (int k = 0; k < npart; k++) {
        const float4* r4 = (const float4*)(g_spart + base + (size_t)k * (NJ * ND));
        float4 v0 = r4[0], v1 = r4[1];
        acc[0] += v0.x; acc[1] += v0.y; acc[2] += v0.z; acc[3] += v0.w;
        acc[4] += v1.x; acc[5] += v1.y; acc[6] += v1.z; acc[7] += v1.w;
    }
#pragma unroll
    for (int k = 0; k < 8; k++) acc[k] *= scale;

    if (t < NJ) s2s[t] = 0.f;
    __syncthreads();
    int dp = t >> 3;
    int j0 = (t & 7) * 4;
#pragma unroll
    for (int q = 0; q < 4; q++)
        atomicAdd(&s2s[j0 + q], acc[2 * q] * acc[2 * q] + acc[2 * q + 1] * acc[2 * q + 1]);
    __syncthreads();

    if (which < 2) {
        float* out = (which == 0) ? g_vj0 : g_vj1;
        float* dst = out + (size_t)b * (NJ * ND) + (size_t)t * 8;
#pragma unroll
        for (int q = 0; q < 4; q++) {
            float s2 = s2s[j0 + q];
            float f = sqrtf(s2) / (1.0f + s2);
            dst[2 * q]     = acc[2 * q] * f;
            dst[2 * q + 1] = acc[2 * q + 1] * f;
        }
    } else {
        float* dst = outext + (size_t)b * (NJ * ND);
#pragma unroll
        for (int q = 0; q < 4; q++) {
            float s2 = s2s[j0 + q];
            float f = sqrtf(s2) / (1.0f + s2);
            dst[(j0 + q) * ND + 2 * dp]     = acc[2 * q] * f;
            dst[(j0 + q) * ND + 2 * dp + 1] = acc[2 * q + 1] * f;
        }
    }
}

// =============================================================================
// K4: fused routing pass v4.  Same pipeline as R7 (register double-buffer
// prefetch, pair-local named barrier, no-max softmax) but PWR=16 and
// grid (16, NB) = 256 CTAs -> one fully-resident wave (no tail).
// =============================================================================
template <int MODE>
__global__ __launch_bounds__(256) void k_route(int which_vj) {
    __shared__ float vj_s[NJ * ND];          // 8 KB permuted
    __shared__ float red[NJ * ND];           // 8 KB CTA partial
    __shared__ float pairbuf[2][4][2][NJ];   // [pi&1][pair][half][j]
    const float* vj_in = (which_vj == 0) ? g_vj0 : g_vj1;
    const int b = blockIdx.y;
    const int t = threadIdx.x;
    {
        const float4* src = (const float4*)(vj_in + (size_t)b * NJ * ND) + t * 2;
        float4 v0 = src[0], v1 = src[1];
        *(float4*)(vj_s + t * 8)     = v0;
        *(float4*)(vj_s + t * 8 + 4) = v1;
#pragma unroll
        for (int k = 0; k < 8; k++) red[t * 8 + k] = 0.f;
    }
    __syncthreads();

    const int warp = t >> 5, jj = t & 31;
    const int pair = warp >> 1, half = warp & 1;
    const int barid = pair + 1;  // named barriers 1..4

    unsigned long long sacc[16];
#pragma unroll
    for (int i = 0; i < 16; i++) sacc[i] = 0ull;

    const int pbase = (blockIdx.x * 4 + pair) * PWR;
    const __half* ubase = g_u + ((size_t)b * NP + pbase) * (NJ * ND)
                              + (size_t)half * 16 * (NJ * 2) + jj * 2;
    const float* vrow = vj_s + (half * 16) * (NJ * 2) + jj * 2;

    __half2 urA[16], urB[16];
#pragma unroll
    for (int dpl = 0; dpl < 16; dpl++)
        urA[dpl] = *(const __half2*)(ubase + (size_t)dpl * (NJ * 2));

    auto body = [&](int pi, __half2 (&cur)[16], __half2 (&nxt)[16]) {
        const int p = pbase + pi;
        if (pi < PWR - 1) {
            const __half* un = ubase + (size_t)(pi + 1) * (NJ * ND);
#pragma unroll
            for (int dpl = 0; dpl < 16; dpl++)
                nxt[dpl] = *(const __half2*)(un + (size_t)dpl * (NJ * 2));
        }
        const size_t bij_off = ((size_t)b * NP + p) * NJ + jj;
        float bijv = 0.f;
        if (MODE == 2) bijv = g_bij[bij_off];  // independent early load

        unsigned long long ag0 = 0ull, ag1 = 0ull;
#pragma unroll
        for (int dpl = 0; dpl < 16; dpl += 2) {
            float2 u0 = __half22float2(cur[dpl]);
            float2 u1 = __half22float2(cur[dpl + 1]);
            ffma2(ag0, pack2(u0.x, u0.y), *(const unsigned long long*)(vrow + (dpl    ) * (NJ * 2)));
            ffma2(ag1, pack2(u1.x, u1.y), *(const unsigned long long*)(vrow + (dpl + 1) * (NJ * 2)));
        }
        float2 f0 = unpack2(ag0), f1 = unpack2(ag1);
        pairbuf[pi & 1][pair][half][jj] = (f0.x + f0.y) + (f1.x + f1.y);
        asm volatile("bar.sync %0, 64;" :: "r"(barid) : "memory");
        float a = pairbuf[pi & 1][pair][0][jj] + pairbuf[pi & 1][pair][1][jj] + bijv;
        if (MODE == 1 && half == 0) g_bij[bij_off] = a;

        // softmax across lanes, no max-shift (|a| <= ~10 -> exp safe in fp32)
        float e = __expf(a);
        float s = e;
#pragma unroll
        for (int off = 16; off; off >>= 1) s += __shfl_xor_sync(0xffffffffu, s, off);
        float c = e / s;

        unsigned long long cp = pack2(c, c);
#pragma unroll
        for (int dpl = 0; dpl < 16; dpl++) {
            float2 uf = __half22float2(cur[dpl]);
            ffma2(sacc[dpl], cp, pack2(uf.x, uf.y));
        }
    };

#pragma unroll
    for (int pi = 0; pi < PWR; pi++) {
        if (pi & 1) body(pi, urB, urA);
        else        body(pi, urA, urB);
    }

    // CTA reduce: each warp adds its dp-half (4 pairs collide -> smem atomics)
#pragma unroll
    for (int dpl = 0; dpl < 16; dpl++) {
        float2 v = unpack2(sacc[dpl]);
        int off = (half * 16 + dpl) * (NJ * 2) + jj * 2;
        atomicAdd(&red[off],     v.x);
        atomicAdd(&red[off + 1], v.y);
    }
    __syncthreads();

    float* dst = g_spart + ((size_t)b * SLOTS + blockIdx.x) * (NJ * ND) + (size_t)t * 8;
    *(float4*)dst       = *(const float4*)(red + t * 8);
    *(float4*)(dst + 4) = *(const float4*)(red + t * 8 + 4);
}

// =============================================================================
extern "C" void kernel_launch(void* const* d_in, const int* in_sizes, int n_in,
                              void* d_out, int out_size) {
    const float* inp  = (const float*)d_in[0];
    const float* W    = (const float*)d_in[1];
    const float* bias = (const float*)d_in[2];
    float* out = (float*)d_out;

    const int k1_smem_bytes = (3 * CHUNK_FLOATS + NE * NB) * (int)sizeof(float);  // 53248
    cudaFuncSetAttribute(k_gemm, cudaFuncAttributeMaxDynamicSharedMemorySize, k1_smem_bytes);

    // u = inp @ W + b   (fp16, permuted, coalesced store, 3-buffer pipeline)
    k_gemm<<<dim3(NP, 4), 128, k1_smem_bytes>>>(inp, W, bias);
    // iteration 0: uniform c -> plain p-sum (64 partials), squash -> vj0
    k_psum<<<dim3(64, NB), 256>>>();
    k_squash<<<NB, 256>>>(1.0f / 32.0f, 0, 64, out);
    // iteration 1
    k_route<1><<<dim3(RCTAB, NB), 256>>>(0);
    k_squash<<<NB, 256>>>(1.0f, 1, RCTAB, out);
    // iteration 2
    k_route<2><<<dim3(RCTAB, NB), 256>>>(1);
    k_squash<<<NB, 256>>>(1.0f, 2, RCTAB, out);
}

// round 9
// speedup vs baseline: 1.2257x; 1.0238x over previous
#include <cuda_runtime.h>
#include <cuda_fp16.h>
#include <cstdint>

// Problem constants
#define NB 16     // batch
#define NP 1024   // primary caps
#define NJ 32     // out caps
#define NE 64     // Dp (contraction)
#define ND 64     // D

// K1 tiling
#define JG 8      // j's per CTA
#define EC 8      // e-chunk; 8 chunks, 3 smem buffers (52 KB -> 4 CTAs/SM)
#define CHUNK_FLOATS (JG * EC * ND)  // 4096 floats = 16 KB

// Route tiling: 256-thread CTAs (8 warps = 4 warp-pairs); a PAIR handles 16 p,
// processed TWO per inner iteration.  grid (16, NB) = 256 CTAs, single wave.
#define RCTAB 16
#define PWR 16

#define SLOTS 64  // spart slots per b (psum uses 64, route uses RCTAB=16)

// u inner-block (2048 elems per (b,p)) is PERMUTED: index(dp,j,par) = dp*64 + j*2 + par
// where d = 2*dp + par.  g_vj0/g_vj1/g_spart use the same permuted layout.

// ---------------- scratch ----------------------------------------------------
__device__ __half g_u[(size_t)NB * NP * NJ * ND];        // 67 MB fp16, permuted
__device__ float g_spart[(size_t)NB * SLOTS * NJ * ND];  // 8.4 MB partials, permuted
__device__ float g_vj0[NB * NJ * ND];                    // permuted
__device__ float g_vj1[NB * NJ * ND];                    // permuted
__device__ float g_bij[NB * NP * NJ];

// ---------------- f32x2 helpers ---------------------------------------------
__device__ __forceinline__ unsigned long long pack2(float x, float y) {
    unsigned long long r;
    asm("mov.b64 %0, {%1,%2};" : "=l"(r) : "f"(x), "f"(y));
    return r;
}
__device__ __forceinline__ float2 unpack2(unsigned long long v) {
    float2 r;
    asm("mov.b64 {%0,%1}, %2;" : "=f"(r.x), "=f"(r.y) : "l"(v));
    return r;
}
__device__ __forceinline__ void ffma2(unsigned long long& acc,
                                      unsigned long long a, unsigned long long b) {
    asm("fma.rn.f32x2 %0, %1, %2, %0;" : "+l"(acc) : "l"(a), "l"(b));
}
__device__ __forceinline__ void cpasync16(void* dst, const void* src) {
    uint32_t s = (uint32_t)__cvta_generic_to_shared(dst);
    asm volatile("cp.async.cg.shared.global [%0], [%1], 16;" :: "r"(s), "l"(src));
}

// =============================================================================
// K1: u[b,p,j,d] = sum_e inp[b,p,e] * W[p,j,e,d] + bias[p,j,d]
// 3-buffer cp.async pipeline, 52 KB smem, regs capped 128 -> 4 CTAs/SM.
// fp16 PERMUTED store via smem staging.
// =============================================================================
extern __shared__ float k1_smem[];

__global__ __launch_bounds__(128, 4) void k_gemm(const float* __restrict__ inp,
                                                 const float* __restrict__ W,
                                                 const float* __restrict__ bias) {
    float* Ws    = k1_smem;                          // [3][JG][EC][ND] = 48 KB
    float* inp_t = k1_smem + 3 * CHUNK_FLOATS;       // [NE][NB], 4 KB

    const int p   = blockIdx.x;
    const int jg  = blockIdx.y;
    const int tid = threadIdx.x;

    {
        int b = tid >> 3, e0 = (tid & 7) << 3;
        const float4* src = (const float4*)(inp + ((size_t)b * NP + p) * NE + e0);
        float4 v0 = src[0], v1 = src[1];
        float v[8] = {v0.x, v0.y, v0.z, v0.w, v1.x, v1.y, v1.z, v1.w};
#pragma unroll
        for (int k = 0; k < 8; k++) inp_t[(e0 + k) * NB + b] = v[k];
    }

    const float* Wbase = W + ((size_t)p * NJ + (size_t)jg * JG) * NE * ND;

    auto prefetch = [&](int c, int buf) {
#pragma unroll
        for (int i = 0; i < 8; i++) {
            int ft  = i * 128 + tid;
            int j   = ft >> 7;
            int rem = ft & 127;
            int el  = rem >> 4;
            int d4  = rem & 15;
            const float* src = Wbase + ((size_t)j * NE + (c * EC + el)) * ND + d4 * 4;
            float* dst = Ws + (size_t)buf * CHUNK_FLOATS + ((size_t)j * EC + el) * ND + d4 * 4;
            cpasync16(dst, src);
        }
        asm volatile("cp.async.commit_group;");
    };

    prefetch(0, 0);
    prefetch(1, 1);
    prefetch(2, 2);
    __syncthreads();  // inp_t ready

    const int jl = tid >> 4;
    const int r  = tid & 15;
    const int b0 = (r & 1) << 3;
    const int d0 = (r >> 1) << 3;

    unsigned long long acc[8][4];
#pragma unroll
    for (int i = 0; i < 8; i++)
#pragma unroll
        for (int k = 0; k < 4; k++) acc[i][k] = 0ull;

    auto compute = [&](int c) {
        const float* wrow = Ws + (size_t)(c % 3) * CHUNK_FLOATS + ((size_t)jl * EC) * ND + d0;
        const float* irow = inp_t + (size_t)(c * EC) * NB + b0;
#pragma unroll
        for (int el = 0; el < EC; el++) {
            const ulonglong2* wp = (const ulonglong2*)(wrow + (size_t)el * ND);
            ulonglong2 w0 = wp[0], w1 = wp[1];
            float4 i0 = *(const float4*)(irow + (size_t)el * NB);
            float4 i1 = *(const float4*)(irow + (size_t)el * NB + 4);
            float ia[8] = {i0.x, i0.y, i0.z, i0.w, i1.x, i1.y, i1.z, i1.w};
#pragma unroll
            for (int bi = 0; bi < 8; bi++) {
                unsigned long long av = pack2(ia[bi], ia[bi]);
                ffma2(acc[bi][0], av, w0.x);
                ffma2(acc[bi][1], av, w0.y);
                ffma2(acc[bi][2], av, w1.x);
                ffma2(acc[bi][3], av, w1.y);
            }
        }
    };

#pragma unroll 1
    for (int c = 0; c < 5; c++) {
        asm volatile("cp.async.wait_group 2;");
        __syncthreads();
        compute(c);
        __syncthreads();               // buffer c%3 free across whole CTA
        prefetch(c + 3, (c + 3) % 3);
    }
    asm volatile("cp.async.wait_group 2;");
    __syncthreads();
    compute(5);
    asm volatile("cp.async.wait_group 1;");
    __syncthreads();
    compute(6);
    asm volatile("cp.async.wait_group 0;");
    __syncthreads();
    compute(7);
    __syncthreads();   // done reading Ws -> reuse smem for staging

    // ---- stage fp16 tile: stage_h2[(b*32 + dp)*8 + jl] ----
    __half2* stage = (__half2*)k1_smem;   // 16 KB
    const int dp0 = d0 >> 1;
    const float* bptr = bias + ((size_t)p * NJ + (jg * JG + jl)) * ND + d0;
    float4 bb0 = *(const float4*)(bptr);
    float4 bb1 = *(const float4*)(bptr + 4);
    float bb[8] = {bb0.x, bb0.y, bb0.z, bb0.w, bb1.x, bb1.y, bb1.z, bb1.w};
#pragma unroll
    for (int bi = 0; bi < 8; bi++) {
        float2 v0 = unpack2(acc[bi][0]);
        float2 v1 = unpack2(acc[bi][1]);
        float2 v2 = unpack2(acc[bi][2]);
        float2 v3 = unpack2(acc[bi][3]);
        float fv[8] = {v0.x, v0.y, v1.x, v1.y, v2.x, v2.y, v3.x, v3.y};
        const int b = b0 + bi;
#pragma unroll
        for (int k = 0; k < 4; k++) {
            stage[((b * 32) + (dp0 + k)) * 8 + jl] =
                __floats2half2_rn(fv[2 * k] + bb[2 * k], fv[2 * k + 1] + bb[2 * k + 1]);
        }
    }
    __syncthreads();

#pragma unroll
    for (int i = 0; i < 8; i++) {
        int idx = i * 128 + tid;
        int b   = idx >> 6;
        int dp  = (idx & 63) >> 1;
        int sel = idx & 1;
        float4 v = *(const float4*)(stage + ((b * 32) + dp) * 8 + sel * 4);
        __half* gdst = g_u + ((size_t)b * NP + p) * (NJ * ND)
                           + (size_t)dp * (NJ * 2) + jg * 16 + sel * 8;
        *(float4*)gdst = v;
    }
}

// =============================================================================
// K2: partial sum over p for iteration 0 (uniform c).  (unchanged)
// =============================================================================
__global__ void k_psum() {
    int ch = blockIdx.x;
    int b  = blockIdx.y;
    int t  = threadIdx.x;
    float acc[8];
#pragma unroll
    for (int k = 0; k < 8; k++) acc[k] = 0.f;
    size_t base = (((size_t)b * NP) + (size_t)ch * 16) * (NJ * ND) + (size_t)t * 8;
#pragma unroll
    for (int pi = 0; pi < 16; pi++) {
        uint4 raw = *(const uint4*)(g_u + base + (size_t)pi * (NJ * ND));
        const __half2* h = (const __half2*)&raw;
#pragma unroll
        for (int k = 0; k < 4; k++) {
            float2 f = __half22float2(h[k]);
            acc[2 * k]     += f.x;
            acc[2 * k + 1] += f.y;
        }
    }
    float* dst = g_spart + ((size_t)b * SLOTS + ch) * (NJ * ND) + (size_t)t * 8;
    *(float4*)dst       = make_float4(acc[0], acc[1], acc[2], acc[3]);
    *(float4*)(dst + 4) = make_float4(acc[4], acc[5], acc[6], acc[7]);
}

// =============================================================================
// K3: reduce npart partials + squash.  (unchanged)
// =============================================================================
__global__ void k_squash(float scale, int which, int npart, float* __restrict__ outext) {
    __shared__ float s2s[NJ];
    int b = blockIdx.x, t = threadIdx.x;
    float acc[8];
#pragma unroll
    for (int k = 0; k < 8; k++) acc[k] = 0.f;
    size_t base = (size_t)b * SLOTS * (NJ * ND) + (size_t)t * 8;
#pragma unroll 4
    for (int k = 0; k < npart; k++) {
        const float4* r4 = (const float4*)(g_spart + base + (size_t)k * (NJ * ND));
        float4 v0 = r4[0], v1 = r4[1];
        acc[0] += v0.x; acc[1] += v0.y; acc[2] += v0.z; acc[3] += v0.w;
        acc[4] += v1.x; acc[5] += v1.y; acc[6] += v1.z; acc[7] += v1.w;
    }
#pragma unroll
    for (int k = 0; k < 8; k++) acc[k] *= scale;

    if (t < NJ) s2s[t] = 0.f;
    __syncthreads();
    int dp = t >> 3;
    int j0 = (t & 7) * 4;
#pragma unroll
    for (int q = 0; q < 4; q++)
        atomicAdd(&s2s[j0 + q], acc[2 * q] * acc[2 * q] + acc[2 * q + 1] * acc[2 * q + 1]);
    __syncthreads();

    if (which < 2) {
        float* out = (which == 0) ? g_vj0 : g_vj1;
        float* dst = out + (size_t)b * (NJ * ND) + (size_t)t * 8;
#pragma unroll
        for (int q = 0; q < 4; q++) {
            float s2 = s2s[j0 + q];
            float f = sqrtf(s2) / (1.0f + s2);
            dst[2 * q]     = acc[2 * q] * f;
            dst[2 * q + 1] = acc[2 * q + 1] * f;
        }
    } else {
        float* dst = outext + (size_t)b * (NJ * ND);
#pragma unroll
        for (int q = 0; q < 4; q++) {
            float s2 = s2s[j0 + q];
            float f = sqrtf(s2) / (1.0f + s2);
            dst[(j0 + q) * ND + 2 * dp]     = acc[2 * q] * f;
            dst[(j0 + q) * ND + 2 * dp + 1] = acc[2 * q + 1] * f;
        }
    }
}

// =============================================================================
// K4: fused routing pass v5.  Warp-pair (lane=j, parity=dp-half) processing
// TWO p per inner iteration: one named barrier + one pairbuf round-trip per
// 2 p, two independent softmax chains in flight.  Register double-buffer
// prefetch of the NEXT pair of p rows.  No-max softmax (|logit| <= ~10).
// grid (RCTAB, NB) = (16,16), 256 threads; pair handles PWR=16 p.
// =============================================================================
template <int MODE>
__global__ __launch_bounds__(256) void k_route(int which_vj) {
    __shared__ float vj_s[NJ * ND];            // 8 KB permuted
    __shared__ float red[NJ * ND];             // 8 KB CTA partial
    __shared__ float pairbuf[2][2][4][2][NJ];  // [iter&1][p01][pair][half][j]
    const float* vj_in = (which_vj == 0) ? g_vj0 : g_vj1;
    const int b = blockIdx.y;
    const int t = threadIdx.x;
    {
        const float4* src = (const float4*)(vj_in + (size_t)b * NJ * ND) + t * 2;
        float4 v0 = src[0], v1 = src[1];
        *(float4*)(vj_s + t * 8)     = v0;
        *(float4*)(vj_s + t * 8 + 4) = v1;
#pragma unroll
        for (int k = 0; k < 8; k++) red[t * 8 + k] = 0.f;
    }
    __syncthreads();

    const int warp = t >> 5, jj = t & 31;
    const int pair = warp >> 1, half = warp & 1;
    const int barid = pair + 1;  // named barriers 1..4

    unsigned long long sacc[16];
#pragma unroll
    for (int i = 0; i < 16; i++) sacc[i] = 0ull;

    const int pbase = (blockIdx.x * 4 + pair) * PWR;
    const __half* ubase = g_u + ((size_t)b * NP + pbase) * (NJ * ND)
                              + (size_t)half * 16 * (NJ * 2) + jj * 2;
    const float* vrow = vj_s + (half * 16) * (NJ * 2) + jj * 2;

    __half2 urA[2][16], urB[2][16];
#pragma unroll
    for (int q = 0; q < 2; q++)
#pragma unroll
        for (int dpl = 0; dpl < 16; dpl++)
            urA[q][dpl] = *(const __half2*)(ubase + (size_t)q * (NJ * ND)
                                                  + (size_t)dpl * (NJ * 2));

    auto body = [&](int pi, __half2 (&cur)[2][16], __half2 (&nxt)[2][16]) {
        // prefetch the NEXT pair of p rows (overlaps everything below)
        if (pi + 2 < PWR) {
#pragma unroll
            for (int q = 0; q < 2; q++) {
                const __half* un = ubase + (size_t)(pi + 2 + q) * (NJ * ND);
#pragma unroll
                for (int dpl = 0; dpl < 16; dpl++)
                    nxt[q][dpl] = *(const __half2*)(un + (size_t)dpl * (NJ * 2));
            }
        }
        const size_t bij0 = ((size_t)b * NP + pbase + pi)     * NJ + jj;
        const size_t bij1 = ((size_t)b * NP + pbase + pi + 1) * NJ + jj;
        float bv0 = 0.f, bv1 = 0.f;
        if (MODE == 2) { bv0 = g_bij[bij0]; bv1 = g_bij[bij1]; }  // early loads

        // partial agreements for both p (4 independent f32x2 chains)
        unsigned long long a00 = 0ull, a01 = 0ull, a10 = 0ull, a11 = 0ull;
#pragma unroll
        for (int dpl = 0; dpl < 16; dpl += 2) {
            unsigned long long v0 = *(const unsigned long long*)(vrow + (dpl    ) * (NJ * 2));
            unsigned long long v1 = *(const unsigned long long*)(vrow + (dpl + 1) * (NJ * 2));
            float2 p00 = __half22float2(cur[0][dpl]);
            float2 p01 = __half22float2(cur[0][dpl + 1]);
            float2 p10 = __half22float2(cur[1][dpl]);
            float2 p11 = __half22float2(cur[1][dpl + 1]);
            ffma2(a00, pack2(p00.x, p00.y), v0);
            ffma2(a01, pack2(p01.x, p01.y), v1);
            ffma2(a10, pack2(p10.x, p10.y), v0);
            ffma2(a11, pack2(p11.x, p11.y), v1);
        }
        float2 f00 = unpack2(a00), f01 = unpack2(a01);
        float2 f10 = unpack2(a10), f11 = unpack2(a11);
        const int ib = (pi >> 1) & 1;
        pairbuf[ib][0][pair][half][jj] = (f00.x + f00.y) + (f01.x + f01.y);
        pairbuf[ib][1][pair][half][jj] = (f10.x + f10.y) + (f11.x + f11.y);
        asm volatile("bar.sync %0, 64;" :: "r"(barid) : "memory");
        float a0 = pairbuf[ib][0][pair][0][jj] + pairbuf[ib][0][pair][1][jj] + bv0;
        float a1 = pairbuf[ib][1][pair][0][jj] + pairbuf[ib][1][pair][1][jj] + bv1;
        if (MODE == 1 && half == 0) { g_bij[bij0] = a0; g_bij[bij1] = a1; }

        // two independent no-max softmaxes across lanes
        float e0 = __expf(a0), e1 = __expf(a1);
        float s0 = e0, s1 = e1;
#pragma unroll
        for (int off = 16; off; off >>= 1) {
            s0 += __shfl_xor_sync(0xffffffffu, s0, off);
            s1 += __shfl_xor_sync(0xffffffffu, s1, off);
        }
        unsigned long long c0 = pack2(e0 / s0, e0 / s0);
        unsigned long long c1 = pack2(e1 / s1, e1 / s1);

#pragma unroll
        for (int dpl = 0; dpl < 16; dpl++) {
            float2 u0 = __half22float2(cur[0][dpl]);
            float2 u1 = __half22float2(cur[1][dpl]);
            ffma2(sacc[dpl], c0, pack2(u0.x, u0.y));
            ffma2(sacc[dpl], c1, pack2(u1.x, u1.y));
        }
    };

#pragma unroll
    for (int pi = 0; pi < PWR; pi += 2) {
        if ((pi >> 1) & 1) body(pi, urB, urA);
        else               body(pi, urA, urB);
    }

    // CTA reduce: each warp adds its dp-half (4 pairs collide -> smem atomics)
#pragma unroll
    for (int dpl = 0; dpl < 16; dpl++) {
        float2 v = unpack2(sacc[dpl]);
        int off = (half * 16 + dpl) * (NJ * 2) + jj * 2;
        atomicAdd(&red[off],     v.x);
        atomicAdd(&red[off + 1], v.y);
    }
    __syncthreads();

    float* dst = g_spart + ((size_t)b * SLOTS + blockIdx.x) * (NJ * ND) + (size_t)t * 8;
    *(float4*)dst       = *(const float4*)(red + t * 8);
    *(float4*)(dst + 4) = *(const float4*)(red + t * 8 + 4);
}

// =============================================================================
extern "C" void kernel_launch(void* const* d_in, const int* in_sizes, int n_in,
                              void* d_out, int out_size) {
    const float* inp  = (const float*)d_in[0];
    const float* W    = (const float*)d_in[1];
    const float* bias = (const float*)d_in[2];
    float* out = (float*)d_out;

    const int k1_smem_bytes = (3 * CHUNK_FLOATS + NE * NB) * (int)sizeof(float);  // 53248
    cudaFuncSetAttribute(k_gemm, cudaFuncAttributeMaxDynamicSharedMemorySize, k1_smem_bytes);

    // u = inp @ W + b   (fp16, permuted, coalesced store, 3-buffer pipeline)
    k_gemm<<<dim3(NP, 4), 128, k1_smem_bytes>>>(inp, W, bias);
    // iteration 0: uniform c -> plain p-sum (64 partials), squash -> vj0
    k_psum<<<dim3(64, NB), 256>>>();
    k_squash<<<NB, 256>>>(1.0f / 32.0f, 0, 64, out);
    // iteration 1
    k_route<1><<<dim3(RCTAB, NB), 256>>>(0);
    k_squash<<<NB, 256>>>(1.0f, 1, RCTAB, out);
    // iteration 2
    k_route<2><<<dim3(RCTAB, NB), 256>>>(1);
    k_squash<<<NB, 256>>>(1.0f, 2, RCTAB, out);
}

// round 10
// speedup vs baseline: 1.2315x; 1.0048x over previous
#include <cuda_runtime.h>
#include <cuda_fp16.h>
#include <cstdint>

// Problem constants
#define NB 16     // batch
#define NP 1024   // primary caps
#define NJ 32     // out caps
#define NE 64     // Dp (contraction)
#define ND 64     // D

// K1 tiling
#define JG 8      // j's per CTA
#define EC 8      // e-chunk; 8 chunks, 3 smem buffers (52 KB -> 4 CTAs/SM)
#define CHUNK_FLOATS (JG * EC * ND)  // 4096 floats = 16 KB

// Route tiling: 256-thread CTAs (8 warps = 4 warp-pairs); a PAIR handles 16 p,
// processed TWO per inner iteration.  grid (16, NB) = 256 CTAs, single wave.
#define RCTAB 16
#define PWR 16

#define SLOTS 64  // spart slots per b (psum uses 64, route uses RCTAB=16)

// u inner-block (2048 elems per (b,p)) is PERMUTED: index(dp,j,par) = dp*64 + j*2 + par
// where d = 2*dp + par.  g_vj0/g_vj1/g_spart use the same permuted layout.

// ---------------- scratch ----------------------------------------------------
__device__ __half g_u[(size_t)NB * NP * NJ * ND];        // 67 MB fp16, permuted
__device__ float g_spart[(size_t)NB * SLOTS * NJ * ND];  // 8.4 MB partials, permuted
__device__ float g_vj0[NB * NJ * ND];                    // permuted
__device__ float g_vj1[NB * NJ * ND];                    // permuted
__device__ float g_bij[NB * NP * NJ];

// ---------------- f32x2 helpers ---------------------------------------------
__device__ __forceinline__ unsigned long long pack2(float x, float y) {
    unsigned long long r;
    asm("mov.b64 %0, {%1,%2};" : "=l"(r) : "f"(x), "f"(y));
    return r;
}
__device__ __forceinline__ float2 unpack2(unsigned long long v) {
    float2 r;
    asm("mov.b64 {%0,%1}, %2;" : "=f"(r.x), "=f"(r.y) : "l"(v));
    return r;
}
__device__ __forceinline__ void ffma2(unsigned long long& acc,
                                      unsigned long long a, unsigned long long b) {
    asm("fma.rn.f32x2 %0, %1, %2, %0;" : "+l"(acc) : "l"(a), "l"(b));
}
__device__ __forceinline__ void cpasync16(void* dst, const void* src) {
    uint32_t s = (uint32_t)__cvta_generic_to_shared(dst);
    asm volatile("cp.async.cg.shared.global [%0], [%1], 16;" :: "r"(s), "l"(src));
}

// =============================================================================
// K1: u[b,p,j,d] = sum_e inp[b,p,e] * W[p,j,e,d] + bias[p,j,d]
// 3-buffer cp.async pipeline, 52 KB smem, regs capped 128 -> 4 CTAs/SM.
// fp16 PERMUTED store via smem staging.
// =============================================================================
extern __shared__ float k1_smem[];

__global__ __launch_bounds__(128, 4) void k_gemm(const float* __restrict__ inp,
                                                 const float* __restrict__ W,
                                                 const float* __restrict__ bias) {
    float* Ws    = k1_smem;                          // [3][JG][EC][ND] = 48 KB
    float* inp_t = k1_smem + 3 * CHUNK_FLOATS;       // [NE][NB], 4 KB

    const int p   = blockIdx.x;
    const int jg  = blockIdx.y;
    const int tid = threadIdx.x;

    {
        int b = tid >> 3, e0 = (tid & 7) << 3;
        const float4* src = (const float4*)(inp + ((size_t)b * NP + p) * NE + e0);
        float4 v0 = src[0], v1 = src[1];
        float v[8] = {v0.x, v0.y, v0.z, v0.w, v1.x, v1.y, v1.z, v1.w};
#pragma unroll
        for (int k = 0; k < 8; k++) inp_t[(e0 + k) * NB + b] = v[k];
    }

    const float* Wbase = W + ((size_t)p * NJ + (size_t)jg * JG) * NE * ND;

    auto prefetch = [&](int c, int buf) {
#pragma unroll
        for (int i = 0; i < 8; i++) {
            int ft  = i * 128 + tid;
            int j   = ft >> 7;
            int rem = ft & 127;
            int el  = rem >> 4;
            int d4  = rem & 15;
            const float* src = Wbase + ((size_t)j * NE + (c * EC + el)) * ND + d4 * 4;
            float* dst = Ws + (size_t)buf * CHUNK_FLOATS + ((size_t)j * EC + el) * ND + d4 * 4;
            cpasync16(dst, src);
        }
        asm volatile("cp.async.commit_group;");
    };

    prefetch(0, 0);
    prefetch(1, 1);
    prefetch(2, 2);
    __syncthreads();  // inp_t ready

    const int jl = tid >> 4;
    const int r  = tid & 15;
    const int b0 = (r & 1) << 3;
    const int d0 = (r >> 1) << 3;

    unsigned long long acc[8][4];
#pragma unroll
    for (int i = 0; i < 8; i++)
#pragma unroll
        for (int k = 0; k < 4; k++) acc[i][k] = 0ull;

    auto compute = [&](int c) {
        const float* wrow = Ws + (size_t)(c % 3) * CHUNK_FLOATS + ((size_t)jl * EC) * ND + d0;
        const float* irow = inp_t + (size_t)(c * EC) * NB + b0;
#pragma unroll
        for (int el = 0; el < EC; el++) {
            const ulonglong2* wp = (const ulonglong2*)(wrow + (size_t)el * ND);
            ulonglong2 w0 = wp[0], w1 = wp[1];
            float4 i0 = *(const float4*)(irow + (size_t)el * NB);
            float4 i1 = *(const float4*)(irow + (size_t)el * NB + 4);
            float ia[8] = {i0.x, i0.y, i0.z, i0.w, i1.x, i1.y, i1.z, i1.w};
#pragma unroll
            for (int bi = 0; bi < 8; bi++) {
                unsigned long long av = pack2(ia[bi], ia[bi]);
                ffma2(acc[bi][0], av, w0.x);
                ffma2(acc[bi][1], av, w0.y);
                ffma2(acc[bi][2], av, w1.x);
                ffma2(acc[bi][3], av, w1.y);
            }
        }
    };

#pragma unroll 1
    for (int c = 0; c < 5; c++) {
        asm volatile("cp.async.wait_group 2;");
        __syncthreads();
        compute(c);
        __syncthreads();               // buffer c%3 free across whole CTA
        prefetch(c + 3, (c + 3) % 3);
    }
    asm volatile("cp.async.wait_group 2;");
    __syncthreads();
    compute(5);
    asm volatile("cp.async.wait_group 1;");
    __syncthreads();
    compute(6);
    asm volatile("cp.async.wait_group 0;");
    __syncthreads();
    compute(7);
    __syncthreads();   // done reading Ws -> reuse smem for staging

    // ---- stage fp16 tile: stage_h2[(b*32 + dp)*8 + jl] ----
    __half2* stage = (__half2*)k1_smem;   // 16 KB
    const int dp0 = d0 >> 1;
    const float* bptr = bias + ((size_t)p * NJ + (jg * JG + jl)) * ND + d0;
    float4 bb0 = *(const float4*)(bptr);
    float4 bb1 = *(const float4*)(bptr + 4);
    float bb[8] = {bb0.x, bb0.y, bb0.z, bb0.w, bb1.x, bb1.y, bb1.z, bb1.w};
#pragma unroll
    for (int bi = 0; bi < 8; bi++) {
        float2 v0 = unpack2(acc[bi][0]);
        float2 v1 = unpack2(acc[bi][1]);
        float2 v2 = unpack2(acc[bi][2]);
        float2 v3 = unpack2(acc[bi][3]);
        float fv[8] = {v0.x, v0.y, v1.x, v1.y, v2.x, v2.y, v3.x, v3.y};
        const int b = b0 + bi;
#pragma unroll
        for (int k = 0; k < 4; k++) {
            stage[((b * 32) + (dp0 + k)) * 8 + jl] =
                __floats2half2_rn(fv[2 * k] + bb[2 * k], fv[2 * k + 1] + bb[2 * k + 1]);
        }
    }
    __syncthreads();

#pragma unroll
    for (int i = 0; i < 8; i++) {
        int idx = i * 128 + tid;
        int b   = idx >> 6;
        int dp  = (idx & 63) >> 1;
        int sel = idx & 1;
        float4 v = *(const float4*)(stage + ((b * 32) + dp) * 8 + sel * 4);
        __half* gdst = g_u + ((size_t)b * NP + p) * (NJ * ND)
                           + (size_t)dp * (NJ * 2) + jg * 16 + sel * 8;
        *(float4*)gdst = v;
    }
}

// =============================================================================
// K2: partial sum over p for iteration 0 (uniform c).  (unchanged)
// =============================================================================
__global__ void k_psum() {
    int ch = blockIdx.x;
    int b  = blockIdx.y;
    int t  = threadIdx.x;
    float acc[8];
#pragma unroll
    for (int k = 0; k < 8; k++) acc[k] = 0.f;
    size_t base = (((size_t)b * NP) + (size_t)ch * 16) * (NJ * ND) + (size_t)t * 8;
#pragma unroll
    for (int pi = 0; pi < 16; pi++) {
        uint4 raw = *(const uint4*)(g_u + base + (size_t)pi * (NJ * ND));
        const __half2* h = (const __half2*)&raw;
#pragma unroll
        for (int k = 0; k < 4; k++) {
            float2 f = __half22float2(h[k]);
            acc[2 * k]     += f.x;
            acc[2 * k + 1] += f.y;
        }
    }
    float* dst = g_spart + ((size_t)b * SLOTS + ch) * (NJ * ND) + (size_t)t * 8;
    *(float4*)dst       = make_float4(acc[0], acc[1], acc[2], acc[3]);
    *(float4*)(dst + 4) = make_float4(acc[4], acc[5], acc[6], acc[7]);
}

// =============================================================================
// K3: reduce npart partials + squash.  (unchanged)
// =============================================================================
__global__ void k_squash(float scale, int which, int npart, float* __restrict__ outext) {
    __shared__ float s2s[NJ];
    int b = blockIdx.x, t = threadIdx.x;
    float acc[8];
#pragma unroll
    for (int k = 0; k < 8; k++) acc[k] = 0.f;
    size_t base = (size_t)b * SLOTS * (NJ * ND) + (size_t)t * 8;
#pragma unroll 4
    for (int k = 0; k < npart; k++) {
        const float4* r4 = (const float4*)(g_spart + base + (size_t)k * (NJ * ND));
        float4 v0 = r4[0], v1 = r4[1];
        acc[0] += v0.x; acc[1] += v0.y; acc[2] += v0.z; acc[3] += v0.w;
        acc[4] += v1.x; acc[5] += v1.y; acc[6] += v1.z; acc[7] += v1.w;
    }
#pragma unroll
    for (int k = 0; k < 8; k++) acc[k] *= scale;

    if (t < NJ) s2s[t] = 0.f;
    __syncthreads();
    int dp = t >> 3;
    int j0 = (t & 7) * 4;
#pragma unroll
    for (int q = 0; q < 4; q++)
        atomicAdd(&s2s[j0 + q], acc[2 * q] * acc[2 * q] + acc[2 * q + 1] * acc[2 * q + 1]);
    __syncthreads();

    if (which < 2) {
        float* out = (which == 0) ? g_vj0 : g_vj1;
        float* dst = out + (size_t)b * (NJ * ND) + (size_t)t * 8;
#pragma unroll
        for (int q = 0; q < 4; q++) {
            float s2 = s2s[j0 + q];
            float f = sqrtf(s2) / (1.0f + s2);
            dst[2 * q]     = acc[2 * q] * f;
            dst[2 * q + 1] = acc[2 * q + 1] * f;
        }
    } else {
        float* dst = outext + (size_t)b * (NJ * ND);
#pragma unroll
        for (int q = 0; q < 4; q++) {
            float s2 = s2s[j0 + q];
            float f = sqrtf(s2) / (1.0f + s2);
            dst[(j0 + q) * ND + 2 * dp]     = acc[2 * q] * f;
            dst[(j0 + q) * ND + 2 * dp + 1] = acc[2 * q + 1] * f;
        }
    }
}

// =============================================================================
// K4: fused routing pass v5.  Warp-pair (lane=j, parity=dp-half) processing
// TWO p per inner iteration: one named barrier + one pairbuf round-trip per
// 2 p, two independent softmax chains in flight.  Register double-buffer
// prefetch of the NEXT pair of p rows.  No-max softmax (|logit| <= ~10).
// grid (RCTAB, NB) = (16,16), 256 threads; pair handles PWR=16 p.
// =============================================================================
template <int MODE>
__global__ __launch_bounds__(256) void k_route(int which_vj) {
    __shared__ float vj_s[NJ * ND];            // 8 KB permuted
    __shared__ float red[NJ * ND];             // 8 KB CTA partial
    __shared__ float pairbuf[2][2][4][2][NJ];  // [iter&1][p01][pair][half][j]
    const float* vj_in = (which_vj == 0) ? g_vj0 : g_vj1;
    const int b = blockIdx.y;
    const int t = threadIdx.x;
    {
        const float4* src = (const float4*)(vj_in + (size_t)b * NJ * ND) + t * 2;
        float4 v0 = src[0], v1 = src[1];
        *(float4*)(vj_s + t * 8)     = v0;
        *(float4*)(vj_s + t * 8 + 4) = v1;
#pragma unroll
        for (int k = 0; k < 8; k++) red[t * 8 + k] = 0.f;
    }
    __syncthreads();

    const int warp = t >> 5, jj = t & 31;
    const int pair = warp >> 1, half = warp & 1;
    const int barid = pair + 1;  // named barriers 1..4

    unsigned long long sacc[16];
#pragma unroll
    for (int i = 0; i < 16; i++) sacc[i] = 0ull;

    const int pbase = (blockIdx.x * 4 + pair) * PWR;
    const __half* ubase = g_u + ((size_t)b * NP + pbase) * (NJ * ND)
                              + (size_t)half * 16 * (NJ * 2) + jj * 2;
    const float* vrow = vj_s + (half * 16) * (NJ * 2) + jj * 2;

    __half2 urA[2][16], urB[2][16];
#pragma unroll
    for (int q = 0; q < 2; q++)
#pragma unroll
        for (int dpl = 0; dpl < 16; dpl++)
            urA[q][dpl] = *(const __half2*)(ubase + (size_t)q * (NJ * ND)
                                                  + (size_t)dpl * (NJ * 2));

    auto body = [&](int pi, __half2 (&cur)[2][16], __half2 (&nxt)[2][16]) {
        // prefetch the NEXT pair of p rows (overlaps everything below)
        if (pi + 2 < PWR) {
#pragma unroll
            for (int q = 0; q < 2; q++) {
                const __half* un = ubase + (size_t)(pi + 2 + q) * (NJ * ND);
#pragma unroll
                for (int dpl = 0; dpl < 16; dpl++)
                    nxt[q][dpl] = *(const __half2*)(un + (size_t)dpl * (NJ * 2));
            }
        }
        const size_t bij0 = ((size_t)b * NP + pbase + pi)     * NJ + jj;
        const size_t bij1 = ((size_t)b * NP + pbase + pi + 1) * NJ + jj;
        float bv0 = 0.f, bv1 = 0.f;
        if (MODE == 2) { bv0 = g_bij[bij0]; bv1 = g_bij[bij1]; }  // early loads

        // partial agreements for both p (4 independent f32x2 chains)
        unsigned long long a00 = 0ull, a01 = 0ull, a10 = 0ull, a11 = 0ull;
#pragma unroll
        for (int dpl = 0; dpl < 16; dpl += 2) {
            unsigned long long v0 = *(const unsigned long long*)(vrow + (dpl    ) * (NJ * 2));
            unsigned long long v1 = *(const unsigned long long*)(vrow + (dpl + 1) * (NJ * 2));
            float2 p00 = __half22float2(cur[0][dpl]);
            float2 p01 = __half22float2(cur[0][dpl + 1]);
            float2 p10 = __half22float2(cur[1][dpl]);
            float2 p11 = __half22float2(cur[1][dpl + 1]);
            ffma2(a00, pack2(p00.x, p00.y), v0);
            ffma2(a01, pack2(p01.x, p01.y), v1);
            ffma2(a10, pack2(p10.x, p10.y), v0);
            ffma2(a11, pack2(p11.x, p11.y), v1);
        }
        float2 f00 = unpack2(a00), f01 = unpack2(a01);
        float2 f10 = unpack2(a10), f11 = unpack2(a11);
        const int ib = (pi >> 1) & 1;
        pairbuf[ib][0][pair][half][jj] = (f00.x + f00.y) + (f01.x + f01.y);
        pairbuf[ib][1][pair][half][jj] = (f10.x + f10.y) + (f11.x + f11.y);
        asm volatile("bar.sync %0, 64;" :: "r"(barid) : "memory");
        float a0 = pairbuf[ib][0][pair][0][jj] + pairbuf[ib][0][pair][1][jj] + bv0;
        float a1 = pairbuf[ib][1][pair][0][jj] + pairbuf[ib][1][pair][1][jj] + bv1;
        if (MODE == 1 && half == 0) { g_bij[bij0] = a0; g_bij[bij1] = a1; }

        // two independent no-max softmaxes across lanes
        float e0 = __expf(a0), e1 = __expf(a1);
        float s0 = e0, s1 = e1;
#pragma unroll
        for (int off = 16; off; off >>= 1) {
            s0 += __shfl_xor_sync(0xffffffffu, s0, off);
            s1 += __shfl_xor_sync(0xffffffffu, s1, off);
        }
        unsigned long long c0 = pack2(e0 / s0, e0 / s0);
        unsigned long long c1 = pack2(e1 / s1, e1 / s1);

#pragma unroll
        for (int dpl = 0; dpl < 16; dpl++) {
            float2 u0 = __half22float2(cur[0][dpl]);
            float2 u1 = __half22float2(cur[1][dpl]);
            ffma2(sacc[dpl], c0, pack2(u0.x, u0.y));
            ffma2(sacc[dpl], c1, pack2(u1.x, u1.y));
        }
    };

#pragma unroll
    for (int pi = 0; pi < PWR; pi += 2) {
        if ((pi >> 1) & 1) body(pi, urB, urA);
        else               body(pi, urA, urB);
    }

    // CTA reduce: each warp adds its dp-half (4 pairs collide -> smem atomics)
#pragma unroll
    for (int dpl = 0; dpl < 16; dpl++) {
        float2 v = unpack2(sacc[dpl]);
        int off = (half * 16 + dpl) * (NJ * 2) + jj * 2;
        atomicAdd(&red[off],     v.x);
        atomicAdd(&red[off + 1], v.y);
    }
    __syncthreads();

    float* dst = g_spart + ((size_t)b * SLOTS + blockIdx.x) * (NJ * ND) + (size_t)t * 8;
    *(float4*)dst       = *(const float4*)(red + t * 8);
    *(float4*)(dst + 4) = *(const float4*)(red + t * 8 + 4);
}

// =============================================================================
extern "C" void kernel_launch(void* const* d_in, const int* in_sizes, int n_in,
                              void* d_out, int out_size) {
    const float* inp  = (const float*)d_in[0];
    const float* W    = (const float*)d_in[1];
    const float* bias = (const float*)d_in[2];
    float* out = (float*)d_out;

    const int k1_smem_bytes = (3 * CHUNK_FLOATS + NE * NB) * (int)sizeof(float);  // 53248
    cudaFuncSetAttribute(k_gemm, cudaFuncAttributeMaxDynamicSharedMemorySize, k1_smem_bytes);

    // u = inp @ W + b   (fp16, permuted, coalesced store, 3-buffer pipeline)
    k_gemm<<<dim3(NP, 4), 128, k1_smem_bytes>>>(inp, W, bias);
    // iteration 0: uniform c -> plain p-sum (64 partials), squash -> vj0
    k_psum<<<dim3(64, NB), 256>>>();
    k_squash<<<NB, 256>>>(1.0f / 32.0f, 0, 64, out);
    // iteration 1
    k_route<1><<<dim3(RCTAB, NB), 256>>>(0);
    k_squash<<<NB, 256>>>(1.0f, 1, RCTAB, out);
    // iteration 2
    k_route<2><<<dim3(RCTAB, NB), 256>>>(1);
    k_squash<<<NB, 256>>>(1.0f, 2, RCTAB, out);
}

// round 11
// speedup vs baseline: 1.2876x; 1.0456x over previous
#include <cuda_runtime.h>
#include <cuda_fp16.h>
#include <cstdint>

// Problem constants
#define NB 16     // batch
#define NP 1024   // primary caps
#define NJ 32     // out caps
#define NE 64     // Dp (contraction)
#define ND 64     // D

// K1 tiling
#define JG 8      // j's per CTA
#define EC 8      // e-chunk; 8 chunks, 3 smem buffers
#define CHUNK_FLOATS (JG * EC * ND)  // 4096 floats = 16 KB

// Route tiling: 256-thread CTAs (8 warps = 4 warp-pairs); a PAIR handles 16 p.
#define RCTAB 16  // route CTAs per b
#define PWR 16    // p per warp-pair

#define SLOTS 64  // spart slots per b (psum uses 64, route uses RCTAB=16)

// u inner-block (2048 elems per (b,p)) is PERMUTED: index(dp,j,par) = dp*64 + j*2 + par
// where d = 2*dp + par.  g_vj0/g_vj1/g_spart use the same permuted layout.

// ---------------- scratch ----------------------------------------------------
__device__ __half g_u[(size_t)NB * NP * NJ * ND];        // 67 MB fp16, permuted
__device__ float g_spart[(size_t)NB * SLOTS * NJ * ND];  // 8.4 MB partials, permuted
__device__ float g_vj0[NB * NJ * ND];                    // permuted
__device__ float g_vj1[NB * NJ * ND];                    // permuted
__device__ float g_bij[NB * NP * NJ];
__device__ int   g_pcnt[NB];   // psum completion counters  (always left at 0)
__device__ int   g_rcnt[NB];   // route completion counters (always left at 0)

// ---------------- f32x2 helpers ---------------------------------------------
__device__ __forceinline__ unsigned long long pack2(float x, float y) {
    unsigned long long r;
    asm("mov.b64 %0, {%1,%2};" : "=l"(r) : "f"(x), "f"(y));
    return r;
}
__device__ __forceinline__ float2 unpack2(unsigned long long v) {
    float2 r;
    asm("mov.b64 {%0,%1}, %2;" : "=f"(r.x), "=f"(r.y) : "l"(v));
    return r;
}
__device__ __forceinline__ void ffma2(unsigned long long& acc,
                                      unsigned long long a, unsigned long long b) {
    asm("fma.rn.f32x2 %0, %1, %2, %0;" : "+l"(acc) : "l"(a), "l"(b));
}
__device__ __forceinline__ void cpasync16(void* dst, const void* src) {
    uint32_t s = (uint32_t)__cvta_generic_to_shared(dst);
    asm volatile("cp.async.cg.shared.global [%0], [%1], 16;" :: "r"(s), "l"(src));
}

// ---------------- fused squash tail (run by the LAST CTA of a producer) ------
// Reduces npart spart slots for batch b, squashes, writes permuted vj (which<2)
// or the standard-layout output (which==2).  256 threads.
__device__ __forceinline__ void squash_tail(int b, int t, float scale, int which,
                                            int npart, float* __restrict__ outext,
                                            float* s2s /* smem[NJ] */) {
    float acc[8];
#pragma unroll
    for (int k = 0; k < 8; k++) acc[k] = 0.f;
    size_t base = (size_t)b * SLOTS * (NJ * ND) + (size_t)t * 8;
#pragma unroll 4
    for (int k = 0; k < npart; k++) {
        const float4* r4 = (const float4*)(g_spart + base + (size_t)k * (NJ * ND));
        float4 v0 = r4[0], v1 = r4[1];
        acc[0] += v0.x; acc[1] += v0.y; acc[2] += v0.z; acc[3] += v0.w;
        acc[4] += v1.x; acc[5] += v1.y; acc[6] += v1.z; acc[7] += v1.w;
    }
#pragma unroll
    for (int k = 0; k < 8; k++) acc[k] *= scale;

    if (t < NJ) s2s[t] = 0.f;
    __syncthreads();
    int dp = t >> 3;
    int j0 = (t & 7) * 4;
#pragma unroll
    for (int q = 0; q < 4; q++)
        atomicAdd(&s2s[j0 + q], acc[2 * q] * acc[2 * q] + acc[2 * q + 1] * acc[2 * q + 1]);
    __syncthreads();

    if (which < 2) {
        float* out = (which == 0) ? g_vj0 : g_vj1;
        float* dst = out + (size_t)b * (NJ * ND) + (size_t)t * 8;
#pragma unroll
        for (int q = 0; q < 4; q++) {
            float s2 = s2s[j0 + q];
            float f = sqrtf(s2) / (1.0f + s2);
            dst[2 * q]     = acc[2 * q] * f;
            dst[2 * q + 1] = acc[2 * q + 1] * f;
        }
    } else {
        float* dst = outext + (size_t)b * (NJ * ND);
#pragma unroll
        for (int q = 0; q < 4; q++) {
            float s2 = s2s[j0 + q];
            float f = sqrtf(s2) / (1.0f + s2);
            dst[(j0 + q) * ND + 2 * dp]     = acc[2 * q] * f;
            dst[(j0 + q) * ND + 2 * dp + 1] = acc[2 * q + 1] * f;
        }
    }
}

// =============================================================================
// K1: u[b,p,j,d] = sum_e inp[b,p,e] * W[p,j,e,d] + bias[p,j,d]
// 3-buffer cp.async pipeline, 52 KB smem, regs capped 128 -> 4 CTAs/SM.
// fp16 PERMUTED store via smem staging.  (unchanged from R10)
// =============================================================================
extern __shared__ float k1_smem[];

__global__ __launch_bounds__(128, 4) void k_gemm(const float* __restrict__ inp,
                                                 const float* __restrict__ W,
                                                 const float* __restrict__ bias) {
    float* Ws    = k1_smem;                          // [3][JG][EC][ND] = 48 KB
    float* inp_t = k1_smem + 3 * CHUNK_FLOATS;       // [NE][NB], 4 KB

    const int p   = blockIdx.x;
    const int jg  = blockIdx.y;
    const int tid = threadIdx.x;

    {
        int b = tid >> 3, e0 = (tid & 7) << 3;
        const float4* src = (const float4*)(inp + ((size_t)b * NP + p) * NE + e0);
        float4 v0 = src[0], v1 = src[1];
        float v[8] = {v0.x, v0.y, v0.z, v0.w, v1.x, v1.y, v1.z, v1.w};
#pragma unroll
        for (int k = 0; k < 8; k++) inp_t[(e0 + k) * NB + b] = v[k];
    }

    const float* Wbase = W + ((size_t)p * NJ + (size_t)jg * JG) * NE * ND;

    auto prefetch = [&](int c, int buf) {
#pragma unroll
        for (int i = 0; i < 8; i++) {
            int ft  = i * 128 + tid;
            int j   = ft >> 7;
            int rem = ft & 127;
            int el  = rem >> 4;
            int d4  = rem & 15;
            const float* src = Wbase + ((size_t)j * NE + (c * EC + el)) * ND + d4 * 4;
            float* dst = Ws + (size_t)buf * CHUNK_FLOATS + ((size_t)j * EC + el) * ND + d4 * 4;
            cpasync16(dst, src);
        }
        asm volatile("cp.async.commit_group;");
    };

    prefetch(0, 0);
    prefetch(1, 1);
    prefetch(2, 2);
    __syncthreads();  // inp_t ready

    const int jl = tid >> 4;
    const int r  = tid & 15;
    const int b0 = (r & 1) << 3;
    const int d0 = (r >> 1) << 3;

    unsigned long long acc[8][4];
#pragma unroll
    for (int i = 0; i < 8; i++)
#pragma unroll
        for (int k = 0; k < 4; k++) acc[i][k] = 0ull;

    auto compute = [&](int c) {
        const float* wrow = Ws + (size_t)(c % 3) * CHUNK_FLOATS + ((size_t)jl * EC) * ND + d0;
        const float* irow = inp_t + (size_t)(c * EC) * NB + b0;
#pragma unroll
        for (int el = 0; el < EC; el++) {
            const ulonglong2* wp = (const ulonglong2*)(wrow + (size_t)el * ND);
            ulonglong2 w0 = wp[0], w1 = wp[1];
            float4 i0 = *(const float4*)(irow + (size_t)el * NB);
            float4 i1 = *(const float4*)(irow + (size_t)el * NB + 4);
            float ia[8] = {i0.x, i0.y, i0.z, i0.w, i1.x, i1.y, i1.z, i1.w};
#pragma unroll
            for (int bi = 0; bi < 8; bi++) {
                unsigned long long av = pack2(ia[bi], ia[bi]);
                ffma2(acc[bi][0], av, w0.x);
                ffma2(acc[bi][1], av, w0.y);
                ffma2(acc[bi][2], av, w1.x);
                ffma2(acc[bi][3], av, w1.y);
            }
        }
    };

#pragma unroll 1
    for (int c = 0; c < 5; c++) {
        asm volatile("cp.async.wait_group 2;");
        __syncthreads();
        compute(c);
        __syncthreads();               // buffer c%3 free across whole CTA
        prefetch(c + 3, (c + 3) % 3);
    }
    asm volatile("cp.async.wait_group 2;");
    __syncthreads();
    compute(5);
    asm volatile("cp.async.wait_group 1;");
    __syncthreads();
    compute(6);
    asm volatile("cp.async.wait_group 0;");
    __syncthreads();
    compute(7);
    __syncthreads();   // done reading Ws -> reuse smem for staging

    // ---- stage fp16 tile: stage_h2[(b*32 + dp)*8 + jl] ----
    __half2* stage = (__half2*)k1_smem;   // 16 KB
    const int dp0 = d0 >> 1;
    const float* bptr = bias + ((size_t)p * NJ + (jg * JG + jl)) * ND + d0;
    float4 bb0 = *(const float4*)(bptr);
    float4 bb1 = *(const float4*)(bptr + 4);
    float bb[8] = {bb0.x, bb0.y, bb0.z, bb0.w, bb1.x, bb1.y, bb1.z, bb1.w};
#pragma unroll
    for (int bi = 0; bi < 8; bi++) {
        float2 v0 = unpack2(acc[bi][0]);
        float2 v1 = unpack2(acc[bi][1]);
        float2 v2 = unpack2(acc[bi][2]);
        float2 v3 = unpack2(acc[bi][3]);
        float fv[8] = {v0.x, v0.y, v1.x, v1.y, v2.x, v2.y, v3.x, v3.y};
        const int b = b0 + bi;
#pragma unroll
        for (int k = 0; k < 4; k++) {
            stage[((b * 32) + (dp0 + k)) * 8 + jl] =
                __floats2half2_rn(fv[2 * k] + bb[2 * k], fv[2 * k + 1] + bb[2 * k + 1]);
        }
    }
    __syncthreads();

#pragma unroll
    for (int i = 0; i < 8; i++) {
        int idx = i * 128 + tid;
        int b   = idx >> 6;
        int dp  = (idx & 63) >> 1;
        int sel = idx & 1;
        float4 v = *(const float4*)(stage + ((b * 32) + dp) * 8 + sel * 4);
        __half* gdst = g_u + ((size_t)b * NP + p) * (NJ * ND)
                           + (size_t)dp * (NJ * 2) + jg * 16 + sel * 8;
        *(float4*)gdst = v;
    }
}

// =============================================================================
// K2: partial sum over p for iteration 0 (uniform c) + FUSED squash by the
// last CTA per b (threadfence-reduction pattern; counter returns to 0).
// =============================================================================
__global__ void k_psum() {
    __shared__ float s2s[NJ];
    __shared__ int s_last;
    int ch = blockIdx.x;
    int b  = blockIdx.y;
    int t  = threadIdx.x;
    float acc[8];
#pragma unroll
    for (int k = 0; k < 8; k++) acc[k] = 0.f;
    size_t base = (((size_t)b * NP) + (size_t)ch * 16) * (NJ * ND) + (size_t)t * 8;
#pragma unroll
    for (int pi = 0; pi < 16; pi++) {
        uint4 raw = *(const uint4*)(g_u + base + (size_t)pi * (NJ * ND));
        const __half2* h = (const __half2*)&raw;
#pragma unroll
        for (int k = 0; k < 4; k++) {
            float2 f = __half22float2(h[k]);
            acc[2 * k]     += f.x;
            acc[2 * k + 1] += f.y;
        }
    }
    float* dst = g_spart + ((size_t)b * SLOTS + ch) * (NJ * ND) + (size_t)t * 8;
    *(float4*)dst       = make_float4(acc[0], acc[1], acc[2], acc[3]);
    *(float4*)(dst + 4) = make_float4(acc[4], acc[5], acc[6], acc[7]);

    __threadfence();
    __syncthreads();
    if (t == 0) {
        int old = atomicAdd(&g_pcnt[b], 1);
        s_last = (old == 64 - 1);
        if (s_last) __threadfence();
    }
    __syncthreads();
    if (s_last) {
        squash_tail(b, t, 1.0f / 32.0f, 0, 64, nullptr, s2s);
        if (t == 0) g_pcnt[b] = 0;   // leave counter at 0 for next replay
    }
}

// =============================================================================
// K4: fused routing pass (R8 pipeline: register double-buffer prefetch,
// pair-local named barrier, no-max softmax) + FUSED squash by last CTA per b.
//   MODE==1: bij_prev = 0, writes bij = agreement; tail writes g_vj1.
//   MODE==2: a = bij_prev + agreement; tail writes d_out.
// grid (RCTAB, NB) = (16,16), 256 threads; pair handles PWR=16 p.
// =============================================================================
template <int MODE>
__global__ __launch_bounds__(256) void k_route(int which_vj, float* __restrict__ outext) {
    __shared__ float vj_s[NJ * ND];          // 8 KB permuted
    __shared__ float red[NJ * ND];           // 8 KB CTA partial
    __shared__ float pairbuf[2][4][2][NJ];   // [pi&1][pair][half][j]
    __shared__ int s_last;
    const float* vj_in = (which_vj == 0) ? g_vj0 : g_vj1;
    const int b = blockIdx.y;
    const int t = threadIdx.x;
    {
        const float4* src = (const float4*)(vj_in + (size_t)b * NJ * ND) + t * 2;
        float4 v0 = src[0], v1 = src[1];
        *(float4*)(vj_s + t * 8)     = v0;
        *(float4*)(vj_s + t * 8 + 4) = v1;
#pragma unroll
        for (int k = 0; k < 8; k++) red[t * 8 + k] = 0.f;
    }
    __syncthreads();

    const int warp = t >> 5, jj = t & 31;
    const int pair = warp >> 1, half = warp & 1;
    const int barid = pair + 1;  // named barriers 1..4

    unsigned long long sacc[16];
#pragma unroll
    for (int i = 0; i < 16; i++) sacc[i] = 0ull;

    const int pbase = (blockIdx.x * 4 + pair) * PWR;
    const __half* ubase = g_u + ((size_t)b * NP + pbase) * (NJ * ND)
                              + (size_t)half * 16 * (NJ * 2) + jj * 2;
    const float* vrow = vj_s + (half * 16) * (NJ * 2) + jj * 2;

    __half2 urA[16], urB[16];
#pragma unroll
    for (int dpl = 0; dpl < 16; dpl++)
        urA[dpl] = *(const __half2*)(ubase + (size_t)dpl * (NJ * 2));

    auto body = [&](int pi, __half2 (&cur)[16], __half2 (&nxt)[16]) {
        const int p = pbase + pi;
        if (pi < PWR - 1) {
            const __half* un = ubase + (size_t)(pi + 1) * (NJ * ND);
#pragma unroll
            for (int dpl = 0; dpl < 16; dpl++)
                nxt[dpl] = *(const __half2*)(un + (size_t)dpl * (NJ * 2));
        }
        const size_t bij_off = ((size_t)b * NP + p) * NJ + jj;
        float bijv = 0.f;
        if (MODE == 2) bijv = g_bij[bij_off];  // independent early load

        unsigned long long ag0 = 0ull, ag1 = 0ull;
#pragma unroll
        for (int dpl = 0; dpl < 16; dpl += 2) {
            float2 u0 = __half22float2(cur[dpl]);
            float2 u1 = __half22float2(cur[dpl + 1]);
            ffma2(ag0, pack2(u0.x, u0.y), *(const unsigned long long*)(vrow + (dpl    ) * (NJ * 2)));
            ffma2(ag1, pack2(u1.x, u1.y), *(const unsigned long long*)(vrow + (dpl + 1) * (NJ * 2)));
        }
        float2 f0 = unpack2(ag0), f1 = unpack2(ag1);
        pairbuf[pi & 1][pair][half][jj] = (f0.x + f0.y) + (f1.x + f1.y);
        asm volatile("bar.sync %0, 64;" :: "r"(barid) : "memory");
        float a = pairbuf[pi & 1][pair][0][jj] + pairbuf[pi & 1][pair][1][jj] + bijv;
        if (MODE == 1 && half == 0) g_bij[bij_off] = a;

        // softmax across lanes, no max-shift (|a| <= ~10 -> exp safe in fp32)
        float e = __expf(a);
        float s = e;
#pragma unroll
        for (int off = 16; off; off >>= 1) s += __shfl_xor_sync(0xffffffffu, s, off);
        float c = e / s;

        unsigned long long cp = pack2(c, c);
#pragma unroll
        for (int dpl = 0; dpl < 16; dpl++) {
            float2 uf = __half22float2(cur[dpl]);
            ffma2(sacc[dpl], cp, pack2(uf.x, uf.y));
        }
    };

#pragma unroll
    for (int pi = 0; pi < PWR; pi++) {
        if (pi & 1) body(pi, urB, urA);
        else        body(pi, urA, urB);
    }

    // CTA reduce: each warp adds its dp-half (4 pairs collide -> smem atomics)
#pragma unroll
    for (int dpl = 0; dpl < 16; dpl++) {
        float2 v = unpack2(sacc[dpl]);
        int off = (half * 16 + dpl) * (NJ * 2) + jj * 2;
        atomicAdd(&red[off],     v.x);
        atomicAdd(&red[off + 1], v.y);
    }
    __syncthreads();

    float* dst = g_spart + ((size_t)b * SLOTS + blockIdx.x) * (NJ * ND) + (size_t)t * 8;
    *(float4*)dst       = *(const float4*)(red + t * 8);
    *(float4*)(dst + 4) = *(const float4*)(red + t * 8 + 4);

    // ---- fused squash by last CTA of this b ----
    __threadfence();
    __syncthreads();
    if (t == 0) {
        int old = atomicAdd(&g_rcnt[b], 1);
        s_last = (old == RCTAB - 1);
        if (s_last) __threadfence();
    }
    __syncthreads();
    if (s_last) {
        // reuse vj_s's smem for the s2s scratch (vj_s no longer needed)
        squash_tail(b, t, 1.0f, (MODE == 1) ? 1 : 2, RCTAB, outext, vj_s);
        if (t == 0) g_rcnt[b] = 0;   // leave counter at 0 for next replay
    }
}

// =============================================================================
extern "C" void kernel_launch(void* const* d_in, const int* in_sizes, int n_in,
                              void* d_out, int out_size) {
    const float* inp  = (const float*)d_in[0];
    const float* W    = (const float*)d_in[1];
    const float* bias = (const float*)d_in[2];
    float* out = (float*)d_out;

    const int k1_smem_bytes = (3 * CHUNK_FLOATS + NE * NB) * (int)sizeof(float);  // 53248
    cudaFuncSetAttribute(k_gemm, cudaFuncAttributeMaxDynamicSharedMemorySize, k1_smem_bytes);

    // u = inp @ W + b   (fp16, permuted, coalesced store, 3-buffer pipeline)
    k_gemm<<<dim3(NP, 4), 128, k1_smem_bytes>>>(inp, W, bias);
    // iteration 0: uniform c -> p-sum + fused squash -> vj0
    k_psum<<<dim3(64, NB), 256>>>();
    // iteration 1: route + fused squash -> vj1
    k_route<1><<<dim3(RCTAB, NB), 256>>>(0, out);
    // iteration 2: route + fused squash -> out
    k_route<2><<<dim3(RCTAB, NB), 256>>>(1, out);
}